// round 1
// baseline (speedup 1.0000x reference)
#include <cuda_runtime.h>
#include <math.h>

#define DM 1024
#define NH 16
#define HD 64
#define BB 4
#define TT 1024
#define SS 4096

// Scratch (allocation-free rule: __device__ globals)
__device__ float g_Q[BB * NH * TT * HD];        // [b][h][t][d]   16 MB
__device__ float g_K[BB * NH * SS * HD];        // [b][h][s][d]   64 MB
__device__ float g_V[BB * NH * SS * HD];        // [b][h][s][d]   64 MB
__device__ float g_attn[BB * TT * DM];          // [b][t][h*64+d] 16 MB

// ---------------------------------------------------------------------------
// Projection GEMM: Y = X @ W^T + bias
//   X: [M, 1024] row-major, W: [1024, 1024] row-major (W[j,k]), N = K = 1024.
//   mode 0: plain Y[row*1024+col]
//   mode 1: Q head-split  -> g_Q[((b*16+h)*1024 + t)*64 + d]   (row=b*1024+t)
//   mode 2: KV head-split -> g_K[((b*16+h)*4096 + s)*64 + d]   (row=b*4096+s)
// Tile: 128x128x16, 256 threads, 8x8 per thread.
// M and N are exact multiples of 128 for every call -> no bounds checks.
// ---------------------------------------------------------------------------
__global__ __launch_bounds__(256) void proj_kernel(
    const float* __restrict__ X, const float* __restrict__ W,
    const float* __restrict__ bias, float* __restrict__ Y, int mode)
{
    __shared__ float As[16][128];
    __shared__ float Bs[16][128];

    const int tid = threadIdx.x;
    const int bn = blockIdx.x * 128;
    const int bm = blockIdx.y * 128;
    const int tx = tid & 15;        // -> output cols tx*8 .. tx*8+7
    const int ty = tid >> 4;        // -> output rows ty*8 .. ty*8+7

    // global-load mapping: 256 threads x 2 float4 each per operand per k-tile
    const int lrow = tid >> 2;          // 0..63  (and lrow+64)
    const int lk   = (tid & 3) * 4;     // 0,4,8,12

    const float* Xp = X + (bm + lrow) * DM + lk;
    const float* Wp = W + (bn + lrow) * DM + lk;

    float acc[8][8];
#pragma unroll
    for (int i = 0; i < 8; i++)
#pragma unroll
        for (int j = 0; j < 8; j++) acc[i][j] = 0.0f;

    // preload k-tile 0
    {
        float4 x0 = *(const float4*)(Xp);
        float4 x1 = *(const float4*)(Xp + 64 * DM);
        float4 w0 = *(const float4*)(Wp);
        float4 w1 = *(const float4*)(Wp + 64 * DM);
        As[lk + 0][lrow] = x0.x;  As[lk + 1][lrow] = x0.y;
        As[lk + 2][lrow] = x0.z;  As[lk + 3][lrow] = x0.w;
        As[lk + 0][lrow + 64] = x1.x;  As[lk + 1][lrow + 64] = x1.y;
        As[lk + 2][lrow + 64] = x1.z;  As[lk + 3][lrow + 64] = x1.w;
        Bs[lk + 0][lrow] = w0.x;  Bs[lk + 1][lrow] = w0.y;
        Bs[lk + 2][lrow] = w0.z;  Bs[lk + 3][lrow] = w0.w;
        Bs[lk + 0][lrow + 64] = w1.x;  Bs[lk + 1][lrow + 64] = w1.y;
        Bs[lk + 2][lrow + 64] = w1.z;  Bs[lk + 3][lrow + 64] = w1.w;
    }
    __syncthreads();

    for (int kt = 0; kt < 64; kt++) {
        float4 x0, x1, w0, w1;
        if (kt < 63) {
            const int ko = (kt + 1) * 16;
            x0 = *(const float4*)(Xp + ko);
            x1 = *(const float4*)(Xp + 64 * DM + ko);
            w0 = *(const float4*)(Wp + ko);
            w1 = *(const float4*)(Wp + 64 * DM + ko);
        }
#pragma unroll
        for (int k = 0; k < 16; k++) {
            float a[8], b[8];
            *(float4*)&a[0] = *(const float4*)&As[k][ty * 8];
            *(float4*)&a[4] = *(const float4*)&As[k][ty * 8 + 4];
            *(float4*)&b[0] = *(const float4*)&Bs[k][tx * 8];
            *(float4*)&b[4] = *(const float4*)&Bs[k][tx * 8 + 4];
#pragma unroll
            for (int i = 0; i < 8; i++)
#pragma unroll
                for (int j = 0; j < 8; j++)
                    acc[i][j] = fmaf(a[i], b[j], acc[i][j]);
        }
        __syncthreads();
        if (kt < 63) {
            As[lk + 0][lrow] = x0.x;  As[lk + 1][lrow] = x0.y;
            As[lk + 2][lrow] = x0.z;  As[lk + 3][lrow] = x0.w;
            As[lk + 0][lrow + 64] = x1.x;  As[lk + 1][lrow + 64] = x1.y;
            As[lk + 2][lrow + 64] = x1.z;  As[lk + 3][lrow + 64] = x1.w;
            Bs[lk + 0][lrow] = w0.x;  Bs[lk + 1][lrow] = w0.y;
            Bs[lk + 2][lrow] = w0.z;  Bs[lk + 3][lrow] = w0.w;
            Bs[lk + 0][lrow + 64] = w1.x;  Bs[lk + 1][lrow + 64] = w1.y;
            Bs[lk + 2][lrow + 64] = w1.z;  Bs[lk + 3][lrow + 64] = w1.w;
        }
        __syncthreads();
    }

    // epilogue: bias + scatter per mode
#pragma unroll
    for (int i = 0; i < 8; i++) {
        const int row = bm + ty * 8 + i;
#pragma unroll
        for (int j = 0; j < 8; j++) {
            const int col = bn + tx * 8 + j;
            const float v = acc[i][j] + __ldg(&bias[col]);
            int dst;
            if (mode == 0) {
                dst = row * DM + col;
            } else if (mode == 1) {
                const int b = row >> 10, t = row & 1023;
                const int h = col >> 6,  d = col & 63;
                dst = ((b * NH + h) * TT + t) * HD + d;
            } else {
                const int b = row >> 12, s = row & 4095;
                const int h = col >> 6,  d = col & 63;
                dst = ((b * NH + h) * SS + s) * HD + d;
            }
            Y[dst] = v;
        }
    }
}

// ---------------------------------------------------------------------------
// Flash attention, one CTA per (b, h, 64-query tile).
// K/V gathered with per-head stride = 1 << (h & 3); S_h = 4096 >> (h & 3).
// 256 threads as 16x16; each thread owns a 4x4 (q x kcol) score microtile and
// a 4x4 (q x dcol) output accumulator. Online softmax; row reductions via
// __shfl_xor across the 16 lanes sharing a q-row (lanes stay in-half-warp).
// ---------------------------------------------------------------------------
#define ATTN_SMEM_FLOATS (4352 + 4352 + 4096 + 4096)   // 16896 floats = 67584 B

__global__ __launch_bounds__(256) void attn_kernel()
{
    extern __shared__ float sm[];
    float* sQt = sm;               // [64 d][68]: sQt[d*68 + q]   (pre-scaled)
    float* sKt = sm + 4352;        // [64 d][68]: sKt[d*68 + kcol]
    float* sV  = sm + 8704;        // [64 k][64]: sV[k*64 + d]
    float* sP  = sm + 12800;       // [64 q][64]: sP[q*64 + k]

    const int tid = threadIdx.x;
    const int tx = tid & 15;       // kcol / dcol group
    const int ty = tid >> 4;       // q-row group
    const int qt = blockIdx.x;
    const int h  = blockIdx.y;
    const int b  = blockIdx.z;
    const int stride = 1 << (h & 3);
    const int nchunk = 64 >> (h & 3);     // S_h / 64

    const float* Qg = g_Q + ((b * NH + h) * TT + qt * 64) * HD;
    const float* Kg = g_K + (b * NH + h) * SS * HD;
    const float* Vg = g_V + (b * NH + h) * SS * HD;

    // Load + transpose Q tile (scaled by 1/sqrt(64) = 0.125)
#pragma unroll
    for (int i = 0; i < 4; i++) {
        const int idx = tid + i * 256;
        const int r  = idx >> 4;
        const int dv = (idx & 15) * 4;
        float4 v = *(const float4*)(Qg + r * 64 + dv);
        sQt[(dv + 0) * 68 + r] = v.x * 0.125f;
        sQt[(dv + 1) * 68 + r] = v.y * 0.125f;
        sQt[(dv + 2) * 68 + r] = v.z * 0.125f;
        sQt[(dv + 3) * 68 + r] = v.w * 0.125f;
    }

    float o[4][4];
    float mrow[4], lsum[4];
#pragma unroll
    for (int i = 0; i < 4; i++) {
        mrow[i] = -INFINITY; lsum[i] = 0.0f;
#pragma unroll
        for (int j = 0; j < 4; j++) o[i][j] = 0.0f;
    }

    for (int kc = 0; kc < nchunk; kc++) {
        __syncthreads();   // previous chunk's PV done before overwriting K/V
        // gather strided K (transposed) and V chunk
#pragma unroll
        for (int i = 0; i < 4; i++) {
            const int idx = tid + i * 256;
            const int r  = idx >> 4;
            const int dv = (idx & 15) * 4;
            const int grow = (kc * 64 + r) * stride;
            float4 kv = *(const float4*)(Kg + grow * 64 + dv);
            sKt[(dv + 0) * 68 + r] = kv.x;
            sKt[(dv + 1) * 68 + r] = kv.y;
            sKt[(dv + 2) * 68 + r] = kv.z;
            sKt[(dv + 3) * 68 + r] = kv.w;
            float4 vv = *(const float4*)(Vg + grow * 64 + dv);
            *(float4*)&sV[r * 64 + dv] = vv;
        }
        __syncthreads();

        // S = Q K^T (scaled)
        float s[4][4];
#pragma unroll
        for (int i = 0; i < 4; i++)
#pragma unroll
            for (int j = 0; j < 4; j++) s[i][j] = 0.0f;

#pragma unroll 16
        for (int d = 0; d < 64; d++) {
            float a[4], kb[4];
            *(float4*)a  = *(const float4*)&sQt[d * 68 + ty * 4];
            *(float4*)kb = *(const float4*)&sKt[d * 68 + tx * 4];
#pragma unroll
            for (int i = 0; i < 4; i++)
#pragma unroll
                for (int j = 0; j < 4; j++)
                    s[i][j] = fmaf(a[i], kb[j], s[i][j]);
        }

        // online softmax per q-row (16 lanes per row, in-half-warp xor tree)
#pragma unroll
        for (int i = 0; i < 4; i++) {
            float mx = fmaxf(fmaxf(s[i][0], s[i][1]), fmaxf(s[i][2], s[i][3]));
#pragma unroll
            for (int off = 8; off; off >>= 1)
                mx = fmaxf(mx, __shfl_xor_sync(0xffffffffu, mx, off));
            const float mnew = fmaxf(mrow[i], mx);
            const float corr = __expf(mrow[i] - mnew);   // 0 on first chunk
            mrow[i] = mnew;
            const float p0 = __expf(s[i][0] - mnew);
            const float p1 = __expf(s[i][1] - mnew);
            const float p2 = __expf(s[i][2] - mnew);
            const float p3 = __expf(s[i][3] - mnew);
            float rs = p0 + p1 + p2 + p3;
#pragma unroll
            for (int off = 8; off; off >>= 1)
                rs += __shfl_xor_sync(0xffffffffu, rs, off);
            lsum[i] = lsum[i] * corr + rs;
#pragma unroll
            for (int j = 0; j < 4; j++) o[i][j] *= corr;
            *(float4*)&sP[(ty * 4 + i) * 64 + tx * 4] = make_float4(p0, p1, p2, p3);
        }
        __syncthreads();

        // O += P V
#pragma unroll 16
        for (int k = 0; k < 64; k++) {
            float vb[4];
            *(float4*)vb = *(const float4*)&sV[k * 64 + tx * 4];
            const float a0 = sP[(ty * 4 + 0) * 64 + k];
            const float a1 = sP[(ty * 4 + 1) * 64 + k];
            const float a2 = sP[(ty * 4 + 2) * 64 + k];
            const float a3 = sP[(ty * 4 + 3) * 64 + k];
#pragma unroll
            for (int j = 0; j < 4; j++) {
                o[0][j] = fmaf(a0, vb[j], o[0][j]);
                o[1][j] = fmaf(a1, vb[j], o[1][j]);
                o[2][j] = fmaf(a2, vb[j], o[2][j]);
                o[3][j] = fmaf(a3, vb[j], o[3][j]);
            }
        }
    }

    // epilogue: normalize, write [b][t][h*64+d]
#pragma unroll
    for (int i = 0; i < 4; i++) {
        const float inv = 1.0f / lsum[i];
        const int t = qt * 64 + ty * 4 + i;
        float4 r = make_float4(o[i][0] * inv, o[i][1] * inv,
                               o[i][2] * inv, o[i][3] * inv);
        *(float4*)&g_attn[(b * TT + t) * DM + h * HD + tx * 4] = r;
    }
}

// ---------------------------------------------------------------------------
extern "C" void kernel_launch(void* const* d_in, const int* in_sizes, int n_in,
                              void* d_out, int out_size)
{
    const float* dec = (const float*)d_in[0];
    const float* enc = (const float*)d_in[1];
    const float* Wq  = (const float*)d_in[2];
    const float* bq  = (const float*)d_in[3];
    const float* Wk  = (const float*)d_in[4];
    const float* bk  = (const float*)d_in[5];
    const float* Wv  = (const float*)d_in[6];
    const float* bv  = (const float*)d_in[7];
    const float* Wo  = (const float*)d_in[8];
    const float* bo  = (const float*)d_in[9];

    float *pQ, *pK, *pV, *pA;
    cudaGetSymbolAddress((void**)&pQ, g_Q);
    cudaGetSymbolAddress((void**)&pK, g_K);
    cudaGetSymbolAddress((void**)&pV, g_V);
    cudaGetSymbolAddress((void**)&pA, g_attn);

    const int attn_smem = ATTN_SMEM_FLOATS * (int)sizeof(float);  // 67584 B
    cudaFuncSetAttribute((const void*)attn_kernel,
                         cudaFuncAttributeMaxDynamicSharedMemorySize, attn_smem);

    dim3 blk(256);
    // projections: N blocks = 1024/128 = 8
    proj_kernel<<<dim3(8, 32),  blk>>>(dec, Wq, bq, pQ, 1);   // M = 4096
    proj_kernel<<<dim3(8, 128), blk>>>(enc, Wk, bk, pK, 2);   // M = 16384
    proj_kernel<<<dim3(8, 128), blk>>>(enc, Wv, bv, pV, 2);   // M = 16384

    attn_kernel<<<dim3(16, NH, BB), blk, attn_smem>>>();

    proj_kernel<<<dim3(8, 32), blk>>>(pA, Wo, bo, (float*)d_out, 0);  // M = 4096
}

// round 3
// speedup vs baseline: 1.5338x; 1.5338x over previous
#include <cuda_runtime.h>
#include <cuda_bf16.h>
#include <math.h>
#include <stdint.h>

#define DM 1024
#define NH 16
#define HD 64
#define BB 4
#define TT 1024
#define SS 4096

// ---------------- scratch (__device__ globals; no allocation allowed) -------
__device__ float g_Q[BB * NH * TT * HD];
__device__ float g_K[BB * NH * SS * HD];
__device__ float g_V[BB * NH * SS * HD];

__device__ __nv_bfloat16 g_dechi[BB * TT * DM], g_declo[BB * TT * DM];
__device__ __nv_bfloat16 g_enchi[BB * SS * DM], g_enclo[BB * SS * DM];
__device__ __nv_bfloat16 g_wqhi[DM * DM], g_wqlo[DM * DM];
__device__ __nv_bfloat16 g_wkhi[DM * DM], g_wklo[DM * DM];
__device__ __nv_bfloat16 g_wvhi[DM * DM], g_wvlo[DM * DM];
__device__ __nv_bfloat16 g_wohi[DM * DM], g_wolo[DM * DM];
__device__ __nv_bfloat16 g_atthi[BB * TT * DM], g_attlo[BB * TT * DM];

// ---------------- helpers ---------------------------------------------------
__device__ __forceinline__ uint32_t smem_u32(const void* p) {
    uint32_t a;
    asm("{ .reg .u64 t; cvta.to.shared.u64 t, %1; cvt.u32.u64 %0, t; }"
        : "=r"(a) : "l"(p));
    return a;
}

#define CP_ASYNC16(sa, ga) \
    asm volatile("cp.async.cg.shared.global [%0], [%1], 16;" \
                 :: "r"(sa), "l"(ga))
#define CP_COMMIT() asm volatile("cp.async.commit_group;" ::: "memory")
#define CP_WAIT1()  asm volatile("cp.async.wait_group 1;" ::: "memory")
#define CP_WAIT0()  asm volatile("cp.async.wait_group 0;" ::: "memory")

#define LDSM_X4(r0, r1, r2, r3, a) \
    asm volatile("ldmatrix.sync.aligned.m8n8.x4.shared.b16 {%0,%1,%2,%3}, [%4];" \
                 : "=r"(r0), "=r"(r1), "=r"(r2), "=r"(r3) : "r"(a))

#define MMA_BF16(c, a, b) \
    asm volatile("mma.sync.aligned.m16n8k16.row.col.f32.bf16.bf16.f32 " \
                 "{%0,%1,%2,%3}, {%4,%5,%6,%7}, {%8,%9}, {%0,%1,%2,%3};" \
                 : "+f"((c)[0]), "+f"((c)[1]), "+f"((c)[2]), "+f"((c)[3]) \
                 : "r"((a)[0]), "r"((a)[1]), "r"((a)[2]), "r"((a)[3]), \
                   "r"((b)[0]), "r"((b)[1]))

// ---------------------------------------------------------------------------
// fp32 -> (bf16 hi, bf16 lo) split
// ---------------------------------------------------------------------------
__global__ void split_kernel(const float* __restrict__ src,
                             __nv_bfloat16* __restrict__ hi,
                             __nv_bfloat16* __restrict__ lo, int n4)
{
    int i = blockIdx.x * blockDim.x + threadIdx.x;
    if (i >= n4) return;
    float4 v = ((const float4*)src)[i];
    __nv_bfloat16 h0 = __float2bfloat16(v.x);
    __nv_bfloat16 h1 = __float2bfloat16(v.y);
    __nv_bfloat16 h2 = __float2bfloat16(v.z);
    __nv_bfloat16 h3 = __float2bfloat16(v.w);
    __nv_bfloat16 l0 = __float2bfloat16(v.x - __bfloat162float(h0));
    __nv_bfloat16 l1 = __float2bfloat16(v.y - __bfloat162float(h1));
    __nv_bfloat16 l2 = __float2bfloat16(v.z - __bfloat162float(h2));
    __nv_bfloat16 l3 = __float2bfloat16(v.w - __bfloat162float(h3));
    __nv_bfloat162* hp = (__nv_bfloat162*)hi;
    __nv_bfloat162* lp = (__nv_bfloat162*)lo;
    hp[2 * i]     = __halves2bfloat162(h0, h1);
    hp[2 * i + 1] = __halves2bfloat162(h2, h3);
    lp[2 * i]     = __halves2bfloat162(l0, l1);
    lp[2 * i + 1] = __halves2bfloat162(l2, l3);
}

// ---------------------------------------------------------------------------
// mma.sync bf16 split GEMM:  Y = (Ahi+Alo) @ (Bhi+Blo)^T + bias
// A: [M,1024] row-major bf16; B: [1024(N),1024(K)] row-major bf16 (= col-major
// K x N, exactly what mma row.col wants). 3 split passes (hh, hl, lh) into one
// fp32 accumulator. CTA 128x128, 8 warps (2M x 4N), warp 64x32, k-chunk 32,
// 3-stage cp.async pipeline.
// ---------------------------------------------------------------------------
#define TSTR 80                    // smem row pitch bytes (32 bf16 + 8 pad)
#define TILE_B (128 * TSTR)        // 10240 B : one 128x32 bf16 tile
#define STAGE_B (4 * TILE_B)       // Ahi|Alo|Bhi|Blo = 40960 B
#define NSTAGE 3
#define GEMM_SMEM (NSTAGE * STAGE_B + 128)
#define NK 32                      // 1024 / 32 k-chunks

__global__ __launch_bounds__(256, 1) void gemm_mma(
    const __nv_bfloat16* __restrict__ Ahi, const __nv_bfloat16* __restrict__ Alo,
    const __nv_bfloat16* __restrict__ Bhi, const __nv_bfloat16* __restrict__ Blo,
    const float* __restrict__ bias, float* __restrict__ Y, int mode)
{
    extern __shared__ char dsm[];
    const uint32_t sb0 = (smem_u32(dsm) + 127) & ~127u;

    const int tid = threadIdx.x;
    const int lane = tid & 31;
    const int wid = tid >> 5;
    const int warpM = wid >> 2;          // 0..1
    const int warpN = wid & 3;           // 0..3
    const int bn = blockIdx.x * 128;
    const int bm = blockIdx.y * 128;

    // ---- global load mapping: 2 chunks of 16B per tile per thread ----------
    int gr[2], gc[2]; uint32_t soff[2];
#pragma unroll
    for (int i = 0; i < 2; i++) {
        const int id = tid + i * 256;
        gr[i] = id >> 2;                 // 0..127
        gc[i] = (id & 3) * 8;            // bf16 col
        soff[i] = (uint32_t)(gr[i] * TSTR + (id & 3) * 16);
    }

    // ---- ldmatrix lane address components ----------------------------------
    // A x4: r = (lane&7) + ((lane>>3)&1)*8 ; kchunk16 = (lane>>4)&1
    const uint32_t aoff = (uint32_t)((warpM * 64 + (lane & 7) + ((lane >> 3) & 1) * 8) * TSTR
                                     + ((lane >> 4) & 1) * 16);
    // B x4: n = (lane&7) + ((lane>>4)&1)*8 ; kchunk16 = (lane>>3)&1
    const uint32_t boff = (uint32_t)((warpN * 32 + (lane & 7) + ((lane >> 4) & 1) * 8) * TSTR
                                     + ((lane >> 3) & 1) * 16);

    float c[4][4][4];
#pragma unroll
    for (int mf = 0; mf < 4; mf++)
#pragma unroll
        for (int nf = 0; nf < 4; nf++)
#pragma unroll
            for (int k = 0; k < 4; k++) c[mf][nf][k] = 0.0f;

    // ---- pipeline ----------------------------------------------------------
    auto issue = [&](int s, int kc) {
        const uint32_t sb = sb0 + s * STAGE_B;
        const int ko = kc * 32;
#pragma unroll
        for (int i = 0; i < 2; i++) {
            const long aoffg = (long)(bm + gr[i]) * DM + ko + gc[i];
            const long boffg = (long)(bn + gr[i]) * DM + ko + gc[i];
            CP_ASYNC16(sb + 0 * TILE_B + soff[i], (const char*)(Ahi + aoffg));
            CP_ASYNC16(sb + 1 * TILE_B + soff[i], (const char*)(Alo + aoffg));
            CP_ASYNC16(sb + 2 * TILE_B + soff[i], (const char*)(Bhi + boffg));
            CP_ASYNC16(sb + 3 * TILE_B + soff[i], (const char*)(Blo + boffg));
        }
        CP_COMMIT();
    };

    issue(0, 0);
    issue(1, 1);

    for (int kt = 0; kt < NK; kt++) {
        if (kt + 1 < NK) CP_WAIT1(); else CP_WAIT0();
        __syncthreads();

        const uint32_t sb = sb0 + (kt % NSTAGE) * STAGE_B;
#pragma unroll
        for (int ks = 0; ks < 2; ks++) {
            const uint32_t kadd = (uint32_t)(ks * 32);
            uint32_t a[4][4], bh[4][2], bl[4][2];
            // A_hi fragments
#pragma unroll
            for (int mf = 0; mf < 4; mf++)
                LDSM_X4(a[mf][0], a[mf][1], a[mf][2], a[mf][3],
                        sb + 0 * TILE_B + aoff + kadd + (uint32_t)(mf * 16 * TSTR));
            // B_hi fragments (2 x4 cover 4 n-frags)
#pragma unroll
            for (int np = 0; np < 2; np++)
                LDSM_X4(bh[np * 2][0], bh[np * 2][1], bh[np * 2 + 1][0], bh[np * 2 + 1][1],
                        sb + 2 * TILE_B + boff + kadd + (uint32_t)(np * 16 * TSTR));
            // B_lo fragments
#pragma unroll
            for (int np = 0; np < 2; np++)
                LDSM_X4(bl[np * 2][0], bl[np * 2][1], bl[np * 2 + 1][0], bl[np * 2 + 1][1],
                        sb + 3 * TILE_B + boff + kadd + (uint32_t)(np * 16 * TSTR));
            // hh + hl
#pragma unroll
            for (int mf = 0; mf < 4; mf++)
#pragma unroll
                for (int nf = 0; nf < 4; nf++) {
                    MMA_BF16(c[mf][nf], a[mf], bh[nf]);
                    MMA_BF16(c[mf][nf], a[mf], bl[nf]);
                }
            // A_lo fragments (reuse regs) + lh
#pragma unroll
            for (int mf = 0; mf < 4; mf++)
                LDSM_X4(a[mf][0], a[mf][1], a[mf][2], a[mf][3],
                        sb + 1 * TILE_B + aoff + kadd + (uint32_t)(mf * 16 * TSTR));
#pragma unroll
            for (int mf = 0; mf < 4; mf++)
#pragma unroll
                for (int nf = 0; nf < 4; nf++)
                    MMA_BF16(c[mf][nf], a[mf], bh[nf]);
        }
        __syncthreads();
        if (kt + 2 < NK) issue((kt + 2) % NSTAGE, kt + 2);
    }

    // ---- epilogue: bias + scatter ------------------------------------------
    const int rb = bm + warpM * 64 + (lane >> 2);
    const int cb = bn + warpN * 32 + (lane & 3) * 2;
#pragma unroll
    for (int mf = 0; mf < 4; mf++) {
#pragma unroll
        for (int nf = 0; nf < 4; nf++) {
            const int col = cb + nf * 8;
            const float b0 = __ldg(&bias[col]);
            const float b1 = __ldg(&bias[col + 1]);
#pragma unroll
            for (int half = 0; half < 2; half++) {
                const int row = rb + mf * 16 + half * 8;
                float2 v;
                v.x = c[mf][nf][half * 2 + 0] + b0;
                v.y = c[mf][nf][half * 2 + 1] + b1;
                int dst;
                if (mode == 0) {
                    dst = row * DM + col;
                } else if (mode == 1) {
                    const int b = row >> 10, t = row & 1023;
                    const int h = col >> 6, d = col & 63;
                    dst = ((b * NH + h) * TT + t) * HD + d;
                } else {
                    const int b = row >> 12, s = row & 4095;
                    const int h = col >> 6, d = col & 63;
                    dst = ((b * NH + h) * SS + s) * HD + d;
                }
                *(float2*)&Y[dst] = v;
            }
        }
    }
}

// ---------------------------------------------------------------------------
// Flash attention (round-1 math, known correct). Epilogue writes bf16 hi/lo
// for the tensor-core O-projection.
// ---------------------------------------------------------------------------
#define ATTN_SMEM_FLOATS (4352 + 4352 + 4096 + 4096)

__global__ __launch_bounds__(256) void attn_kernel()
{
    extern __shared__ float sm[];
    float* sQt = sm;
    float* sKt = sm + 4352;
    float* sV  = sm + 8704;
    float* sP  = sm + 12800;

    const int tid = threadIdx.x;
    const int tx = tid & 15;
    const int ty = tid >> 4;
    const int qt = blockIdx.x;
    const int h  = blockIdx.y;
    const int b  = blockIdx.z;
    const int stride = 1 << (h & 3);
    const int nchunk = 64 >> (h & 3);

    const float* Qg = g_Q + ((b * NH + h) * TT + qt * 64) * HD;
    const float* Kg = g_K + (b * NH + h) * SS * HD;
    const float* Vg = g_V + (b * NH + h) * SS * HD;

#pragma unroll
    for (int i = 0; i < 4; i++) {
        const int idx = tid + i * 256;
        const int r = idx >> 4;
        const int dv = (idx & 15) * 4;
        float4 v = *(const float4*)(Qg + r * 64 + dv);
        sQt[(dv + 0) * 68 + r] = v.x * 0.125f;
        sQt[(dv + 1) * 68 + r] = v.y * 0.125f;
        sQt[(dv + 2) * 68 + r] = v.z * 0.125f;
        sQt[(dv + 3) * 68 + r] = v.w * 0.125f;
    }

    float o[4][4];
    float mrow[4], lsum[4];
#pragma unroll
    for (int i = 0; i < 4; i++) {
        mrow[i] = -INFINITY; lsum[i] = 0.0f;
#pragma unroll
        for (int j = 0; j < 4; j++) o[i][j] = 0.0f;
    }

    for (int kc = 0; kc < nchunk; kc++) {
        __syncthreads();
#pragma unroll
        for (int i = 0; i < 4; i++) {
            const int idx = tid + i * 256;
            const int r = idx >> 4;
            const int dv = (idx & 15) * 4;
            const int grow = (kc * 64 + r) * stride;
            float4 kv = *(const float4*)(Kg + grow * 64 + dv);
            sKt[(dv + 0) * 68 + r] = kv.x;
            sKt[(dv + 1) * 68 + r] = kv.y;
            sKt[(dv + 2) * 68 + r] = kv.z;
            sKt[(dv + 3) * 68 + r] = kv.w;
            float4 vv = *(const float4*)(Vg + grow * 64 + dv);
            *(float4*)&sV[r * 64 + dv] = vv;
        }
        __syncthreads();

        float s[4][4];
#pragma unroll
        for (int i = 0; i < 4; i++)
#pragma unroll
            for (int j = 0; j < 4; j++) s[i][j] = 0.0f;

#pragma unroll 16
        for (int d = 0; d < 64; d++) {
            float a[4], kb[4];
            *(float4*)a  = *(const float4*)&sQt[d * 68 + ty * 4];
            *(float4*)kb = *(const float4*)&sKt[d * 68 + tx * 4];
#pragma unroll
            for (int i = 0; i < 4; i++)
#pragma unroll
                for (int j = 0; j < 4; j++)
                    s[i][j] = fmaf(a[i], kb[j], s[i][j]);
        }

#pragma unroll
        for (int i = 0; i < 4; i++) {
            float mx = fmaxf(fmaxf(s[i][0], s[i][1]), fmaxf(s[i][2], s[i][3]));
#pragma unroll
            for (int off = 8; off; off >>= 1)
                mx = fmaxf(mx, __shfl_xor_sync(0xffffffffu, mx, off));
            const float mnew = fmaxf(mrow[i], mx);
            const float corr = __expf(mrow[i] - mnew);
            mrow[i] = mnew;
            const float p0 = __expf(s[i][0] - mnew);
            const float p1 = __expf(s[i][1] - mnew);
            const float p2 = __expf(s[i][2] - mnew);
            const float p3 = __expf(s[i][3] - mnew);
            float rs = p0 + p1 + p2 + p3;
#pragma unroll
            for (int off = 8; off; off >>= 1)
                rs += __shfl_xor_sync(0xffffffffu, rs, off);
            lsum[i] = lsum[i] * corr + rs;
#pragma unroll
            for (int j = 0; j < 4; j++) o[i][j] *= corr;
            *(float4*)&sP[(ty * 4 + i) * 64 + tx * 4] = make_float4(p0, p1, p2, p3);
        }
        __syncthreads();

#pragma unroll 16
        for (int k = 0; k < 64; k++) {
            float vb[4];
            *(float4*)vb = *(const float4*)&sV[k * 64 + tx * 4];
            const float a0 = sP[(ty * 4 + 0) * 64 + k];
            const float a1 = sP[(ty * 4 + 1) * 64 + k];
            const float a2 = sP[(ty * 4 + 2) * 64 + k];
            const float a3 = sP[(ty * 4 + 3) * 64 + k];
#pragma unroll
            for (int j = 0; j < 4; j++) {
                o[0][j] = fmaf(a0, vb[j], o[0][j]);
                o[1][j] = fmaf(a1, vb[j], o[1][j]);
                o[2][j] = fmaf(a2, vb[j], o[2][j]);
                o[3][j] = fmaf(a3, vb[j], o[3][j]);
            }
        }
    }

#pragma unroll
    for (int i = 0; i < 4; i++) {
        const float inv = 1.0f / lsum[i];
        const int t = qt * 64 + ty * 4 + i;
        const int off = (b * TT + t) * DM + h * HD + tx * 4;
        float r0 = o[i][0] * inv, r1 = o[i][1] * inv;
        float r2 = o[i][2] * inv, r3 = o[i][3] * inv;
        __nv_bfloat16 h0 = __float2bfloat16(r0);
        __nv_bfloat16 h1 = __float2bfloat16(r1);
        __nv_bfloat16 h2 = __float2bfloat16(r2);
        __nv_bfloat16 h3 = __float2bfloat16(r3);
        __nv_bfloat16 l0 = __float2bfloat16(r0 - __bfloat162float(h0));
        __nv_bfloat16 l1 = __float2bfloat16(r1 - __bfloat162float(h1));
        __nv_bfloat16 l2 = __float2bfloat16(r2 - __bfloat162float(h2));
        __nv_bfloat16 l3 = __float2bfloat16(r3 - __bfloat162float(h3));
        ((__nv_bfloat162*)(g_atthi + off))[0] = __halves2bfloat162(h0, h1);
        ((__nv_bfloat162*)(g_atthi + off))[1] = __halves2bfloat162(h2, h3);
        ((__nv_bfloat162*)(g_attlo + off))[0] = __halves2bfloat162(l0, l1);
        ((__nv_bfloat162*)(g_attlo + off))[1] = __halves2bfloat162(l2, l3);
    }
}

// ---------------------------------------------------------------------------
extern "C" void kernel_launch(void* const* d_in, const int* in_sizes, int n_in,
                              void* d_out, int out_size)
{
    const float* dec = (const float*)d_in[0];
    const float* enc = (const float*)d_in[1];
    const float* Wq  = (const float*)d_in[2];
    const float* bq  = (const float*)d_in[3];
    const float* Wk  = (const float*)d_in[4];
    const float* bk  = (const float*)d_in[5];
    const float* Wv  = (const float*)d_in[6];
    const float* bv  = (const float*)d_in[7];
    const float* Wo  = (const float*)d_in[8];
    const float* bo  = (const float*)d_in[9];

    float *pQ, *pK, *pV;
    cudaGetSymbolAddress((void**)&pQ, g_Q);
    cudaGetSymbolAddress((void**)&pK, g_K);
    cudaGetSymbolAddress((void**)&pV, g_V);
    __nv_bfloat16 *dh, *dl, *eh, *el, *qh, *ql, *kh, *kl, *vh, *vl, *oh, *ol, *ah, *al;
    cudaGetSymbolAddress((void**)&dh, g_dechi);  cudaGetSymbolAddress((void**)&dl, g_declo);
    cudaGetSymbolAddress((void**)&eh, g_enchi);  cudaGetSymbolAddress((void**)&el, g_enclo);
    cudaGetSymbolAddress((void**)&qh, g_wqhi);   cudaGetSymbolAddress((void**)&ql, g_wqlo);
    cudaGetSymbolAddress((void**)&kh, g_wkhi);   cudaGetSymbolAddress((void**)&kl, g_wklo);
    cudaGetSymbolAddress((void**)&vh, g_wvhi);   cudaGetSymbolAddress((void**)&vl, g_wvlo);
    cudaGetSymbolAddress((void**)&oh, g_wohi);   cudaGetSymbolAddress((void**)&ol, g_wolo);
    cudaGetSymbolAddress((void**)&ah, g_atthi);  cudaGetSymbolAddress((void**)&al, g_attlo);

    cudaFuncSetAttribute((const void*)gemm_mma,
                         cudaFuncAttributeMaxDynamicSharedMemorySize, GEMM_SMEM);
    const int attn_smem = ATTN_SMEM_FLOATS * (int)sizeof(float);
    cudaFuncSetAttribute((const void*)attn_kernel,
                         cudaFuncAttributeMaxDynamicSharedMemorySize, attn_smem);

    split_kernel<<<(BB * TT * DM / 4 + 255) / 256, 256>>>(dec, dh, dl, BB * TT * DM / 4);
    split_kernel<<<(BB * SS * DM / 4 + 255) / 256, 256>>>(enc, eh, el, BB * SS * DM / 4);
    split_kernel<<<(DM * DM / 4 + 255) / 256, 256>>>(Wq, qh, ql, DM * DM / 4);
    split_kernel<<<(DM * DM / 4 + 255) / 256, 256>>>(Wk, kh, kl, DM * DM / 4);
    split_kernel<<<(DM * DM / 4 + 255) / 256, 256>>>(Wv, vh, vl, DM * DM / 4);
    split_kernel<<<(DM * DM / 4 + 255) / 256, 256>>>(Wo, oh, ol, DM * DM / 4);

    gemm_mma<<<dim3(8, 32),  256, GEMM_SMEM>>>(dh, dl, qh, ql, bq, pQ, 1);
    gemm_mma<<<dim3(8, 128), 256, GEMM_SMEM>>>(eh, el, kh, kl, bk, pK, 2);
    gemm_mma<<<dim3(8, 128), 256, GEMM_SMEM>>>(eh, el, vh, vl, bv, pV, 2);

    attn_kernel<<<dim3(16, NH, BB), 256, attn_smem>>>();

    gemm_mma<<<dim3(8, 32), 256, GEMM_SMEM>>>(ah, al, oh, ol, bo, (float*)d_out, 0);
}

// round 5
// speedup vs baseline: 2.5190x; 1.6423x over previous
#include <cuda_runtime.h>
#include <cuda_bf16.h>
#include <math.h>
#include <stdint.h>

#define DM 1024
#define NH 16
#define HD 64
#define BB 4
#define TT 1024
#define SS 4096

#define SCALE_Q 0.1803368801111204f   // 0.125 * log2(e)

// ---------------- scratch (__device__ globals) ------------------------------
__device__ __nv_bfloat16 g_qhi[BB * NH * TT * HD], g_qlo[BB * NH * TT * HD];
__device__ __nv_bfloat16 g_khi[BB * NH * SS * HD], g_klo[BB * NH * SS * HD];
__device__ __nv_bfloat16 g_vhi[BB * NH * SS * HD], g_vlo[BB * NH * SS * HD];

__device__ __nv_bfloat16 g_dechi[BB * TT * DM], g_declo[BB * TT * DM];
__device__ __nv_bfloat16 g_enchi[BB * SS * DM], g_enclo[BB * SS * DM];
__device__ __nv_bfloat16 g_wqhi[DM * DM], g_wqlo[DM * DM];
__device__ __nv_bfloat16 g_wkhi[DM * DM], g_wklo[DM * DM];
__device__ __nv_bfloat16 g_wvhi[DM * DM], g_wvlo[DM * DM];
__device__ __nv_bfloat16 g_wohi[DM * DM], g_wolo[DM * DM];
__device__ __nv_bfloat16 g_atthi[BB * TT * DM], g_attlo[BB * TT * DM];

// ---------------- helpers ---------------------------------------------------
__device__ __forceinline__ uint32_t smem_u32(const void* p) {
    uint32_t a;
    asm("{ .reg .u64 t; cvta.to.shared.u64 t, %1; cvt.u32.u64 %0, t; }"
        : "=r"(a) : "l"(p));
    return a;
}
__device__ __forceinline__ float ex2f(float x) {
    float y;
    asm("ex2.approx.ftz.f32 %0, %1;" : "=f"(y) : "f"(x));
    return y;
}

#define CP_ASYNC16(sa, ga) \
    asm volatile("cp.async.cg.shared.global [%0], [%1], 16;" :: "r"(sa), "l"(ga))
#define CP_COMMIT() asm volatile("cp.async.commit_group;" ::: "memory")
#define CP_WAIT1()  asm volatile("cp.async.wait_group 1;" ::: "memory")
#define CP_WAIT0()  asm volatile("cp.async.wait_group 0;" ::: "memory")

#define LDSM_X4(r0, r1, r2, r3, a) \
    asm volatile("ldmatrix.sync.aligned.m8n8.x4.shared.b16 {%0,%1,%2,%3}, [%4];" \
                 : "=r"(r0), "=r"(r1), "=r"(r2), "=r"(r3) : "r"(a))
#define LDSM_X4_T(r0, r1, r2, r3, a) \
    asm volatile("ldmatrix.sync.aligned.m8n8.x4.trans.shared.b16 {%0,%1,%2,%3}, [%4];" \
                 : "=r"(r0), "=r"(r1), "=r"(r2), "=r"(r3) : "r"(a))

#define MMA_BF16(c, a, b) \
    asm volatile("mma.sync.aligned.m16n8k16.row.col.f32.bf16.bf16.f32 " \
                 "{%0,%1,%2,%3}, {%4,%5,%6,%7}, {%8,%9}, {%0,%1,%2,%3};" \
                 : "+f"((c)[0]), "+f"((c)[1]), "+f"((c)[2]), "+f"((c)[3]) \
                 : "r"((a)[0]), "r"((a)[1]), "r"((a)[2]), "r"((a)[3]), \
                   "r"((b)[0]), "r"((b)[1]))
#define MMA_BF16_2(c, a, b0, b1) \
    asm volatile("mma.sync.aligned.m16n8k16.row.col.f32.bf16.bf16.f32 " \
                 "{%0,%1,%2,%3}, {%4,%5,%6,%7}, {%8,%9}, {%0,%1,%2,%3};" \
                 : "+f"((c)[0]), "+f"((c)[1]), "+f"((c)[2]), "+f"((c)[3]) \
                 : "r"((a)[0]), "r"((a)[1]), "r"((a)[2]), "r"((a)[3]), \
                   "r"(b0), "r"(b1))

__device__ __forceinline__ uint32_t pack_hi2(float v0, float v1,
                                             float& r0, float& r1) {
    __nv_bfloat16 h0 = __float2bfloat16(v0);
    __nv_bfloat16 h1 = __float2bfloat16(v1);
    r0 = v0 - __bfloat162float(h0);
    r1 = v1 - __bfloat162float(h1);
    __nv_bfloat162 t = __halves2bfloat162(h0, h1);
    return *(uint32_t*)&t;
}
__device__ __forceinline__ uint32_t pack_bf2(float v0, float v1) {
    __nv_bfloat162 t = __halves2bfloat162(__float2bfloat16(v0), __float2bfloat16(v1));
    return *(uint32_t*)&t;
}

// ---------------------------------------------------------------------------
// fp32 -> (bf16 hi, bf16 lo) split
// ---------------------------------------------------------------------------
__global__ void split_kernel(const float* __restrict__ src,
                             __nv_bfloat16* __restrict__ hi,
                             __nv_bfloat16* __restrict__ lo, int n4)
{
    int i = blockIdx.x * blockDim.x + threadIdx.x;
    if (i >= n4) return;
    float4 v = ((const float4*)src)[i];
    float r0, r1, r2, r3;
    uint32_t h01 = pack_hi2(v.x, v.y, r0, r1);
    uint32_t h23 = pack_hi2(v.z, v.w, r2, r3);
    ((uint32_t*)hi)[2 * i]     = h01;
    ((uint32_t*)hi)[2 * i + 1] = h23;
    ((uint32_t*)lo)[2 * i]     = pack_bf2(r0, r1);
    ((uint32_t*)lo)[2 * i + 1] = pack_bf2(r2, r3);
}

// ---------------------------------------------------------------------------
// mma.sync bf16 split GEMM:  Y = ((Ahi+Alo) @ (Bhi+Blo)^T + bias) * scale
// mode 0: fp32 out, plain [row][col]; mode 1: Q head-split bf16 hi/lo (scaled);
// mode 2: KV head-split bf16 hi/lo.
// ---------------------------------------------------------------------------
#define TSTR 80
#define TILE_B (128 * TSTR)
#define STAGE_B (4 * TILE_B)
#define NSTAGE 3
#define GEMM_SMEM (NSTAGE * STAGE_B + 128)
#define NK 32

__global__ __launch_bounds__(256, 1) void gemm_mma(
    const __nv_bfloat16* __restrict__ Ahi, const __nv_bfloat16* __restrict__ Alo,
    const __nv_bfloat16* __restrict__ Bhi, const __nv_bfloat16* __restrict__ Blo,
    const float* __restrict__ bias, float* __restrict__ Yf,
    __nv_bfloat16* __restrict__ Yhi, __nv_bfloat16* __restrict__ Ylo,
    float scale, int mode)
{
    extern __shared__ char dsm[];
    const uint32_t sb0 = (smem_u32(dsm) + 127) & ~127u;

    const int tid = threadIdx.x;
    const int lane = tid & 31;
    const int wid = tid >> 5;
    const int warpM = wid >> 2;
    const int warpN = wid & 3;
    const int bn = blockIdx.x * 128;
    const int bm = blockIdx.y * 128;

    int gr[2], gc[2]; uint32_t soff[2];
#pragma unroll
    for (int i = 0; i < 2; i++) {
        const int id = tid + i * 256;
        gr[i] = id >> 2;
        gc[i] = (id & 3) * 8;
        soff[i] = (uint32_t)(gr[i] * TSTR + (id & 3) * 16);
    }

    const uint32_t aoff = (uint32_t)((warpM * 64 + (lane & 7) + ((lane >> 3) & 1) * 8) * TSTR
                                     + ((lane >> 4) & 1) * 16);
    const uint32_t boff = (uint32_t)((warpN * 32 + (lane & 7) + ((lane >> 4) & 1) * 8) * TSTR
                                     + ((lane >> 3) & 1) * 16);

    float c[4][4][4];
#pragma unroll
    for (int mf = 0; mf < 4; mf++)
#pragma unroll
        for (int nf = 0; nf < 4; nf++)
#pragma unroll
            for (int k = 0; k < 4; k++) c[mf][nf][k] = 0.0f;

    auto issue = [&](int s, int kc) {
        const uint32_t sb = sb0 + s * STAGE_B;
        const int ko = kc * 32;
#pragma unroll
        for (int i = 0; i < 2; i++) {
            const long aoffg = (long)(bm + gr[i]) * DM + ko + gc[i];
            const long boffg = (long)(bn + gr[i]) * DM + ko + gc[i];
            CP_ASYNC16(sb + 0 * TILE_B + soff[i], (const char*)(Ahi + aoffg));
            CP_ASYNC16(sb + 1 * TILE_B + soff[i], (const char*)(Alo + aoffg));
            CP_ASYNC16(sb + 2 * TILE_B + soff[i], (const char*)(Bhi + boffg));
            CP_ASYNC16(sb + 3 * TILE_B + soff[i], (const char*)(Blo + boffg));
        }
        CP_COMMIT();
    };

    issue(0, 0);
    issue(1, 1);

    for (int kt = 0; kt < NK; kt++) {
        if (kt + 1 < NK) CP_WAIT1(); else CP_WAIT0();
        __syncthreads();

        const uint32_t sb = sb0 + (kt % NSTAGE) * STAGE_B;
#pragma unroll
        for (int ks = 0; ks < 2; ks++) {
            const uint32_t kadd = (uint32_t)(ks * 32);
            uint32_t a[4][4], bh[4][2], bl[4][2];
#pragma unroll
            for (int mf = 0; mf < 4; mf++)
                LDSM_X4(a[mf][0], a[mf][1], a[mf][2], a[mf][3],
                        sb + 0 * TILE_B + aoff + kadd + (uint32_t)(mf * 16 * TSTR));
#pragma unroll
            for (int np = 0; np < 2; np++)
                LDSM_X4(bh[np * 2][0], bh[np * 2][1], bh[np * 2 + 1][0], bh[np * 2 + 1][1],
                        sb + 2 * TILE_B + boff + kadd + (uint32_t)(np * 16 * TSTR));
#pragma unroll
            for (int np = 0; np < 2; np++)
                LDSM_X4(bl[np * 2][0], bl[np * 2][1], bl[np * 2 + 1][0], bl[np * 2 + 1][1],
                        sb + 3 * TILE_B + boff + kadd + (uint32_t)(np * 16 * TSTR));
#pragma unroll
            for (int mf = 0; mf < 4; mf++)
#pragma unroll
                for (int nf = 0; nf < 4; nf++) {
                    MMA_BF16(c[mf][nf], a[mf], bh[nf]);
                    MMA_BF16(c[mf][nf], a[mf], bl[nf]);
                }
#pragma unroll
            for (int mf = 0; mf < 4; mf++)
                LDSM_X4(a[mf][0], a[mf][1], a[mf][2], a[mf][3],
                        sb + 1 * TILE_B + aoff + kadd + (uint32_t)(mf * 16 * TSTR));
#pragma unroll
            for (int mf = 0; mf < 4; mf++)
#pragma unroll
                for (int nf = 0; nf < 4; nf++)
                    MMA_BF16(c[mf][nf], a[mf], bh[nf]);
        }
        __syncthreads();
        if (kt + 2 < NK) issue((kt + 2) % NSTAGE, kt + 2);
    }

    // epilogue
    const int rb = bm + warpM * 64 + (lane >> 2);
    const int cb = bn + warpN * 32 + (lane & 3) * 2;
#pragma unroll
    for (int mf = 0; mf < 4; mf++) {
#pragma unroll
        for (int nf = 0; nf < 4; nf++) {
            const int col = cb + nf * 8;
            const float b0 = __ldg(&bias[col]);
            const float b1 = __ldg(&bias[col + 1]);
#pragma unroll
            for (int half = 0; half < 2; half++) {
                const int row = rb + mf * 16 + half * 8;
                float v0 = (c[mf][nf][half * 2 + 0] + b0) * scale;
                float v1 = (c[mf][nf][half * 2 + 1] + b1) * scale;
                if (mode == 0) {
                    float2 v; v.x = v0; v.y = v1;
                    *(float2*)&Yf[row * DM + col] = v;
                } else {
                    int dst;
                    if (mode == 1) {
                        const int b = row >> 10, t = row & 1023;
                        const int h = col >> 6, d = col & 63;
                        dst = ((b * NH + h) * TT + t) * HD + d;
                    } else {
                        const int b = row >> 12, s = row & 4095;
                        const int h = col >> 6, d = col & 63;
                        dst = ((b * NH + h) * SS + s) * HD + d;
                    }
                    float r0, r1;
                    uint32_t hp = pack_hi2(v0, v1, r0, r1);
                    *(uint32_t*)(Yhi + dst) = hp;
                    *(uint32_t*)(Ylo + dst) = pack_bf2(r0, r1);
                }
            }
        }
    }
}

// ---------------------------------------------------------------------------
// Tensor-core flash attention.
// CTA: 128 q-rows (8 warps x m16), 64-key chunks, K/V hi/lo double-buffered.
// S = (Qhi+Qlo)(Khi+Klo)^T (3 passes), online softmax (exp2; scale folded
// into Q), P split hi/lo in regs, O += (Phi+Plo)(Vhi+Vlo) (3 passes).
// ---------------------------------------------------------------------------
#define APITCH 144
#define KVARR (64 * APITCH)        // 9216
#define ASTG (4 * KVARR)           // 36864: Kh|Kl|Vh|Vl
#define AQ_B (128 * APITCH)        // 18432 per Q array
#define ATT_SMEM (2 * AQ_B + 2 * ASTG + 128)

__global__ __launch_bounds__(256, 1) void attn_mma()
{
    extern __shared__ char asm_[];
    const uint32_t sb = (smem_u32(asm_) + 127) & ~127u;
    const uint32_t sQh = sb, sQl = sb + AQ_B;
    const uint32_t sStg = sb + 2 * AQ_B;

    const int tid = threadIdx.x;
    const int lane = tid & 31;
    const int wid = tid >> 5;
    const int qt = blockIdx.x;
    const int h  = blockIdx.y;
    const int b  = blockIdx.z;
    const int stride = 1 << (h & 3);
    const int nchunk = 64 >> (h & 3);

    const __nv_bfloat16* Qh = g_qhi + ((size_t)(b * NH + h) * TT + qt * 128) * HD;
    const __nv_bfloat16* Ql = g_qlo + ((size_t)(b * NH + h) * TT + qt * 128) * HD;
    const size_t kvbase = (size_t)(b * NH + h) * SS * HD;

    auto issue_kv = [&](int st, int kc) {
        const uint32_t s0 = sStg + st * ASTG;
#pragma unroll
        for (int i = 0; i < 2; i++) {
            const int idx = tid + i * 256;
            const int row = idx >> 3, cc = idx & 7;
            const size_t g = kvbase + (size_t)((kc * 64 + row) * stride) * HD + cc * 8;
            const uint32_t d = (uint32_t)(row * APITCH + cc * 16);
            CP_ASYNC16(s0 + 0 * KVARR + d, (const char*)(g_khi + g));
            CP_ASYNC16(s0 + 1 * KVARR + d, (const char*)(g_klo + g));
            CP_ASYNC16(s0 + 2 * KVARR + d, (const char*)(g_vhi + g));
            CP_ASYNC16(s0 + 3 * KVARR + d, (const char*)(g_vlo + g));
        }
        CP_COMMIT();
    };

    // Q loads (group shared with chunk 0)
#pragma unroll
    for (int i = 0; i < 4; i++) {
        const int idx = tid + i * 256;
        const int row = idx >> 3, cc = idx & 7;
        const uint32_t d = (uint32_t)(row * APITCH + cc * 16);
        CP_ASYNC16(sQh + d, (const char*)(Qh + row * HD + cc * 8));
        CP_ASYNC16(sQl + d, (const char*)(Ql + row * HD + cc * 8));
    }
    issue_kv(0, 0);
    issue_kv(1, 1);

    const uint32_t aoff = (uint32_t)((wid * 16 + (lane & 7) + ((lane >> 3) & 1) * 8) * APITCH
                                     + ((lane >> 4) & 1) * 16);
    const uint32_t koff = (uint32_t)(((lane & 7) + ((lane >> 4) & 1) * 8) * APITCH
                                     + ((lane >> 3) & 1) * 16);
    const uint32_t voff = (uint32_t)((lane & 15) * APITCH + (lane >> 4) * 16);

    uint32_t ah[4][4], al[4][4];
    float o[8][4];
#pragma unroll
    for (int nf = 0; nf < 8; nf++)
#pragma unroll
        for (int k = 0; k < 4; k++) o[nf][k] = 0.0f;
    float m0 = -1e30f, m1 = -1e30f, l0 = 0.0f, l1 = 0.0f;

    for (int kc = 0; kc < nchunk; kc++) {
        if (kc + 1 < nchunk) CP_WAIT1(); else CP_WAIT0();
        __syncthreads();

        if (kc == 0) {
#pragma unroll
            for (int ks = 0; ks < 4; ks++) {
                LDSM_X4(ah[ks][0], ah[ks][1], ah[ks][2], ah[ks][3], sQh + aoff + ks * 32);
                LDSM_X4(al[ks][0], al[ks][1], al[ks][2], al[ks][3], sQl + aoff + ks * 32);
            }
        }

        const uint32_t s0 = sStg + (kc & 1) * ASTG;

        // ---- S = Q K^T (3 split passes) -----------------------------------
        float S[8][4];
#pragma unroll
        for (int nf = 0; nf < 8; nf++)
#pragma unroll
            for (int k = 0; k < 4; k++) S[nf][k] = 0.0f;

#pragma unroll
        for (int ks = 0; ks < 4; ks++) {
#pragma unroll
            for (int np = 0; np < 4; np++) {
                uint32_t k0, k1, k2, k3;
                const uint32_t ka = koff + (uint32_t)(np * 16 * APITCH) + ks * 32;
                LDSM_X4(k0, k1, k2, k3, s0 + 0 * KVARR + ka);
                MMA_BF16_2(S[2 * np],     ah[ks], k0, k1);
                MMA_BF16_2(S[2 * np + 1], ah[ks], k2, k3);
                MMA_BF16_2(S[2 * np],     al[ks], k0, k1);
                MMA_BF16_2(S[2 * np + 1], al[ks], k2, k3);
                LDSM_X4(k0, k1, k2, k3, s0 + 1 * KVARR + ka);
                MMA_BF16_2(S[2 * np],     ah[ks], k0, k1);
                MMA_BF16_2(S[2 * np + 1], ah[ks], k2, k3);
            }
        }

        // ---- online softmax (rows r=lane>>2 and r+8) ----------------------
        float mx0 = -1e30f, mx1 = -1e30f;
#pragma unroll
        for (int nf = 0; nf < 8; nf++) {
            mx0 = fmaxf(mx0, fmaxf(S[nf][0], S[nf][1]));
            mx1 = fmaxf(mx1, fmaxf(S[nf][2], S[nf][3]));
        }
        mx0 = fmaxf(mx0, __shfl_xor_sync(0xffffffffu, mx0, 1));
        mx0 = fmaxf(mx0, __shfl_xor_sync(0xffffffffu, mx0, 2));
        mx1 = fmaxf(mx1, __shfl_xor_sync(0xffffffffu, mx1, 1));
        mx1 = fmaxf(mx1, __shfl_xor_sync(0xffffffffu, mx1, 2));
        const float mn0 = fmaxf(m0, mx0), mn1 = fmaxf(m1, mx1);
        const float sc0 = ex2f(m0 - mn0), sc1 = ex2f(m1 - mn1);
        m0 = mn0; m1 = mn1;
        l0 *= sc0; l1 *= sc1;
#pragma unroll
        for (int nf = 0; nf < 8; nf++) {
            o[nf][0] *= sc0; o[nf][1] *= sc0;
            o[nf][2] *= sc1; o[nf][3] *= sc1;
        }

        uint32_t ph[4][4], pl[4][4];
#pragma unroll
        for (int nf = 0; nf < 8; nf++) {
            const float p0 = ex2f(S[nf][0] - mn0);
            const float p1 = ex2f(S[nf][1] - mn0);
            const float p2 = ex2f(S[nf][2] - mn1);
            const float p3 = ex2f(S[nf][3] - mn1);
            l0 += p0 + p1; l1 += p2 + p3;
            const int ks = nf >> 1, sl = (nf & 1) * 2;
            float r0, r1, r2, r3;
            ph[ks][sl + 0] = pack_hi2(p0, p1, r0, r1);
            ph[ks][sl + 1] = pack_hi2(p2, p3, r2, r3);
            pl[ks][sl + 0] = pack_bf2(r0, r1);
            pl[ks][sl + 1] = pack_bf2(r2, r3);
        }

        // ---- O += P V (3 split passes, V via ldmatrix.trans) --------------
#pragma unroll
        for (int ks = 0; ks < 4; ks++) {
#pragma unroll
            for (int nd = 0; nd < 4; nd++) {
                uint32_t v0, v1, v2, v3;
                const uint32_t va = voff + (uint32_t)(ks * 16 * APITCH) + (uint32_t)(nd * 32);
                LDSM_X4_T(v0, v1, v2, v3, s0 + 2 * KVARR + va);
                MMA_BF16_2(o[2 * nd],     ph[ks], v0, v1);
                MMA_BF16_2(o[2 * nd + 1], ph[ks], v2, v3);
                MMA_BF16_2(o[2 * nd],     pl[ks], v0, v1);
                MMA_BF16_2(o[2 * nd + 1], pl[ks], v2, v3);
                LDSM_X4_T(v0, v1, v2, v3, s0 + 3 * KVARR + va);
                MMA_BF16_2(o[2 * nd],     ph[ks], v0, v1);
                MMA_BF16_2(o[2 * nd + 1], ph[ks], v2, v3);
            }
        }

        __syncthreads();
        if (kc + 2 < nchunk) issue_kv(kc & 1, kc + 2);
    }

    // ---- epilogue: normalize, write bf16 hi/lo for the O projection -------
    l0 += __shfl_xor_sync(0xffffffffu, l0, 1);
    l0 += __shfl_xor_sync(0xffffffffu, l0, 2);
    l1 += __shfl_xor_sync(0xffffffffu, l1, 1);
    l1 += __shfl_xor_sync(0xffffffffu, l1, 2);
    const float inv0 = 1.0f / l0, inv1 = 1.0f / l1;
    const int t0 = qt * 128 + wid * 16 + (lane >> 2);
    const size_t base0 = (size_t)(b * TT + t0) * DM + h * HD;
    const size_t base1 = base0 + 8 * DM;
#pragma unroll
    for (int nf = 0; nf < 8; nf++) {
        const int d = nf * 8 + (lane & 3) * 2;
        float r0, r1;
        uint32_t hp = pack_hi2(o[nf][0] * inv0, o[nf][1] * inv0, r0, r1);
        *(uint32_t*)(g_atthi + base0 + d) = hp;
        *(uint32_t*)(g_attlo + base0 + d) = pack_bf2(r0, r1);
        hp = pack_hi2(o[nf][2] * inv1, o[nf][3] * inv1, r0, r1);
        *(uint32_t*)(g_atthi + base1 + d) = hp;
        *(uint32_t*)(g_attlo + base1 + d) = pack_bf2(r0, r1);
    }
}

// ---------------------------------------------------------------------------
extern "C" void kernel_launch(void* const* d_in, const int* in_sizes, int n_in,
                              void* d_out, int out_size)
{
    const float* dec = (const float*)d_in[0];
    const float* enc = (const float*)d_in[1];
    const float* Wq  = (const float*)d_in[2];
    const float* bq  = (const float*)d_in[3];
    const float* Wk  = (const float*)d_in[4];
    const float* bk  = (const float*)d_in[5];
    const float* Wv  = (const float*)d_in[6];
    const float* bv  = (const float*)d_in[7];
    const float* Wo  = (const float*)d_in[8];
    const float* bo  = (const float*)d_in[9];

    __nv_bfloat16 *qh_, *ql_, *kh_, *kl_, *vh_, *vl_;
    cudaGetSymbolAddress((void**)&qh_, g_qhi);  cudaGetSymbolAddress((void**)&ql_, g_qlo);
    cudaGetSymbolAddress((void**)&kh_, g_khi);  cudaGetSymbolAddress((void**)&kl_, g_klo);
    cudaGetSymbolAddress((void**)&vh_, g_vhi);  cudaGetSymbolAddress((void**)&vl_, g_vlo);
    __nv_bfloat16 *dh, *dl, *eh, *el, *wqh, *wql, *wkh, *wkl, *wvh, *wvl, *woh, *wol, *ah, *al;
    cudaGetSymbolAddress((void**)&dh, g_dechi);  cudaGetSymbolAddress((void**)&dl, g_declo);
    cudaGetSymbolAddress((void**)&eh, g_enchi);  cudaGetSymbolAddress((void**)&el, g_enclo);
    cudaGetSymbolAddress((void**)&wqh, g_wqhi);  cudaGetSymbolAddress((void**)&wql, g_wqlo);
    cudaGetSymbolAddress((void**)&wkh, g_wkhi);  cudaGetSymbolAddress((void**)&wkl, g_wklo);
    cudaGetSymbolAddress((void**)&wvh, g_wvhi);  cudaGetSymbolAddress((void**)&wvl, g_wvlo);
    cudaGetSymbolAddress((void**)&woh, g_wohi);  cudaGetSymbolAddress((void**)&wol, g_wolo);
    cudaGetSymbolAddress((void**)&ah, g_atthi);  cudaGetSymbolAddress((void**)&al, g_attlo);

    cudaFuncSetAttribute((const void*)gemm_mma,
                         cudaFuncAttributeMaxDynamicSharedMemorySize, GEMM_SMEM);
    cudaFuncSetAttribute((const void*)attn_mma,
                         cudaFuncAttributeMaxDynamicSharedMemorySize, ATT_SMEM);

    split_kernel<<<(BB * TT * DM / 4 + 255) / 256, 256>>>(dec, dh, dl, BB * TT * DM / 4);
    split_kernel<<<(BB * SS * DM / 4 + 255) / 256, 256>>>(enc, eh, el, BB * SS * DM / 4);
    split_kernel<<<(DM * DM / 4 + 255) / 256, 256>>>(Wq, wqh, wql, DM * DM / 4);
    split_kernel<<<(DM * DM / 4 + 255) / 256, 256>>>(Wk, wkh, wkl, DM * DM / 4);
    split_kernel<<<(DM * DM / 4 + 255) / 256, 256>>>(Wv, wvh, wvl, DM * DM / 4);
    split_kernel<<<(DM * DM / 4 + 255) / 256, 256>>>(Wo, woh, wol, DM * DM / 4);

    gemm_mma<<<dim3(8, 32),  256, GEMM_SMEM>>>(dh, dl, wqh, wql, bq,
                                               nullptr, qh_, ql_, SCALE_Q, 1);
    gemm_mma<<<dim3(8, 128), 256, GEMM_SMEM>>>(eh, el, wkh, wkl, bk,
                                               nullptr, kh_, kl_, 1.0f, 2);
    gemm_mma<<<dim3(8, 128), 256, GEMM_SMEM>>>(eh, el, wvh, wvl, bv,
                                               nullptr, vh_, vl_, 1.0f, 2);

    attn_mma<<<dim3(TT / 128, NH, BB), 256, ATT_SMEM>>>();

    gemm_mma<<<dim3(8, 32), 256, GEMM_SMEM>>>(ah, al, woh, wol, bo,
                                              (float*)d_out, nullptr, nullptr, 1.0f, 0);
}

// round 6
// speedup vs baseline: 3.3100x; 1.3140x over previous
#include <cuda_runtime.h>
#include <cuda_bf16.h>
#include <math.h>
#include <stdint.h>

#define DM 1024
#define NH 16
#define HD 64
#define BB 4
#define TT 1024
#define SS 4096

#define SCALE_Q 0.1803368801111204f   // 0.125 * log2(e)

// ---------------- scratch (__device__ globals) ------------------------------
__device__ __nv_bfloat16 g_qhi[BB * NH * TT * HD], g_qlo[BB * NH * TT * HD];
__device__ __nv_bfloat16 g_khi[BB * NH * SS * HD], g_klo[BB * NH * SS * HD];
__device__ __nv_bfloat16 g_vhi[BB * NH * SS * HD], g_vlo[BB * NH * SS * HD];

__device__ __nv_bfloat16 g_dechi[BB * TT * DM], g_declo[BB * TT * DM];
__device__ __nv_bfloat16 g_enchi[BB * SS * DM], g_enclo[BB * SS * DM];
__device__ __nv_bfloat16 g_wqhi[DM * DM], g_wqlo[DM * DM];
__device__ __nv_bfloat16 g_wkhi[DM * DM], g_wklo[DM * DM];
__device__ __nv_bfloat16 g_wvhi[DM * DM], g_wvlo[DM * DM];
__device__ __nv_bfloat16 g_wohi[DM * DM], g_wolo[DM * DM];
__device__ __nv_bfloat16 g_atthi[BB * TT * DM], g_attlo[BB * TT * DM];

// ---------------- helpers ---------------------------------------------------
__device__ __forceinline__ uint32_t smem_u32(const void* p) {
    uint32_t a;
    asm("{ .reg .u64 t; cvta.to.shared.u64 t, %1; cvt.u32.u64 %0, t; }"
        : "=r"(a) : "l"(p));
    return a;
}
__device__ __forceinline__ float ex2f(float x) {
    float y;
    asm("ex2.approx.ftz.f32 %0, %1;" : "=f"(y) : "f"(x));
    return y;
}

#define CP_ASYNC16(sa, ga) \
    asm volatile("cp.async.cg.shared.global [%0], [%1], 16;" :: "r"(sa), "l"(ga))
#define CP_COMMIT() asm volatile("cp.async.commit_group;" ::: "memory")
#define CP_WAIT1()  asm volatile("cp.async.wait_group 1;" ::: "memory")
#define CP_WAIT0()  asm volatile("cp.async.wait_group 0;" ::: "memory")

#define LDSM_X4(r0, r1, r2, r3, a) \
    asm volatile("ldmatrix.sync.aligned.m8n8.x4.shared.b16 {%0,%1,%2,%3}, [%4];" \
                 : "=r"(r0), "=r"(r1), "=r"(r2), "=r"(r3) : "r"(a))
#define LDSM_X4_T(r0, r1, r2, r3, a) \
    asm volatile("ldmatrix.sync.aligned.m8n8.x4.trans.shared.b16 {%0,%1,%2,%3}, [%4];" \
                 : "=r"(r0), "=r"(r1), "=r"(r2), "=r"(r3) : "r"(a))

#define MMA_BF16(c, a, b) \
    asm volatile("mma.sync.aligned.m16n8k16.row.col.f32.bf16.bf16.f32 " \
                 "{%0,%1,%2,%3}, {%4,%5,%6,%7}, {%8,%9}, {%0,%1,%2,%3};" \
                 : "+f"((c)[0]), "+f"((c)[1]), "+f"((c)[2]), "+f"((c)[3]) \
                 : "r"((a)[0]), "r"((a)[1]), "r"((a)[2]), "r"((a)[3]), \
                   "r"((b)[0]), "r"((b)[1]))
#define MMA_BF16_2(c, a, b0, b1) \
    asm volatile("mma.sync.aligned.m16n8k16.row.col.f32.bf16.bf16.f32 " \
                 "{%0,%1,%2,%3}, {%4,%5,%6,%7}, {%8,%9}, {%0,%1,%2,%3};" \
                 : "+f"((c)[0]), "+f"((c)[1]), "+f"((c)[2]), "+f"((c)[3]) \
                 : "r"((a)[0]), "r"((a)[1]), "r"((a)[2]), "r"((a)[3]), \
                   "r"(b0), "r"(b1))

__device__ __forceinline__ uint32_t pack_hi2(float v0, float v1,
                                             float& r0, float& r1) {
    __nv_bfloat16 h0 = __float2bfloat16(v0);
    __nv_bfloat16 h1 = __float2bfloat16(v1);
    r0 = v0 - __bfloat162float(h0);
    r1 = v1 - __bfloat162float(h1);
    __nv_bfloat162 t = __halves2bfloat162(h0, h1);
    return *(uint32_t*)&t;
}
__device__ __forceinline__ uint32_t pack_bf2(float v0, float v1) {
    __nv_bfloat162 t = __halves2bfloat162(__float2bfloat16(v0), __float2bfloat16(v1));
    return *(uint32_t*)&t;
}

// ---------------------------------------------------------------------------
// fp32 -> (bf16 hi, bf16 lo) split
// ---------------------------------------------------------------------------
__global__ void split_kernel(const float* __restrict__ src,
                             __nv_bfloat16* __restrict__ hi,
                             __nv_bfloat16* __restrict__ lo, int n4)
{
    int i = blockIdx.x * blockDim.x + threadIdx.x;
    if (i >= n4) return;
    float4 v = ((const float4*)src)[i];
    float r0, r1, r2, r3;
    uint32_t h01 = pack_hi2(v.x, v.y, r0, r1);
    uint32_t h23 = pack_hi2(v.z, v.w, r2, r3);
    ((uint32_t*)hi)[2 * i]     = h01;
    ((uint32_t*)hi)[2 * i + 1] = h23;
    ((uint32_t*)lo)[2 * i]     = pack_bf2(r0, r1);
    ((uint32_t*)lo)[2 * i + 1] = pack_bf2(r2, r3);
}

// ---------------------------------------------------------------------------
// mma.sync bf16 split GEMM (dense):  Y = ((Ahi+Alo) @ (Bhi+Blo)^T + bias)*scale
// mode 0: fp32 out plain; mode 1: Q head-split bf16 hi/lo (scaled).
// ---------------------------------------------------------------------------
#define TSTR 80
#define TILE_B (128 * TSTR)
#define STAGE_B (4 * TILE_B)
#define NSTAGE 3
#define GEMM_SMEM (NSTAGE * STAGE_B + 128)
#define NK 32

__global__ __launch_bounds__(256, 1) void gemm_mma(
    const __nv_bfloat16* __restrict__ Ahi, const __nv_bfloat16* __restrict__ Alo,
    const __nv_bfloat16* __restrict__ Bhi, const __nv_bfloat16* __restrict__ Blo,
    const float* __restrict__ bias, float* __restrict__ Yf,
    __nv_bfloat16* __restrict__ Yhi, __nv_bfloat16* __restrict__ Ylo,
    float scale, int mode)
{
    extern __shared__ char dsm[];
    const uint32_t sb0 = (smem_u32(dsm) + 127) & ~127u;

    const int tid = threadIdx.x;
    const int lane = tid & 31;
    const int wid = tid >> 5;
    const int warpM = wid >> 2;
    const int warpN = wid & 3;
    const int bn = blockIdx.x * 128;
    const int bm = blockIdx.y * 128;

    int gr[2], gc[2]; uint32_t soff[2];
#pragma unroll
    for (int i = 0; i < 2; i++) {
        const int id = tid + i * 256;
        gr[i] = id >> 2;
        gc[i] = (id & 3) * 8;
        soff[i] = (uint32_t)(gr[i] * TSTR + (id & 3) * 16);
    }

    const uint32_t aoff = (uint32_t)((warpM * 64 + (lane & 7) + ((lane >> 3) & 1) * 8) * TSTR
                                     + ((lane >> 4) & 1) * 16);
    const uint32_t boff = (uint32_t)((warpN * 32 + (lane & 7) + ((lane >> 4) & 1) * 8) * TSTR
                                     + ((lane >> 3) & 1) * 16);

    float c[4][4][4];
#pragma unroll
    for (int mf = 0; mf < 4; mf++)
#pragma unroll
        for (int nf = 0; nf < 4; nf++)
#pragma unroll
            for (int k = 0; k < 4; k++) c[mf][nf][k] = 0.0f;

    auto issue = [&](int s, int kc) {
        const uint32_t sb = sb0 + s * STAGE_B;
        const int ko = kc * 32;
#pragma unroll
        for (int i = 0; i < 2; i++) {
            const long aoffg = (long)(bm + gr[i]) * DM + ko + gc[i];
            const long boffg = (long)(bn + gr[i]) * DM + ko + gc[i];
            CP_ASYNC16(sb + 0 * TILE_B + soff[i], (const char*)(Ahi + aoffg));
            CP_ASYNC16(sb + 1 * TILE_B + soff[i], (const char*)(Alo + aoffg));
            CP_ASYNC16(sb + 2 * TILE_B + soff[i], (const char*)(Bhi + boffg));
            CP_ASYNC16(sb + 3 * TILE_B + soff[i], (const char*)(Blo + boffg));
        }
        CP_COMMIT();
    };

    issue(0, 0);
    issue(1, 1);

    for (int kt = 0; kt < NK; kt++) {
        if (kt + 1 < NK) CP_WAIT1(); else CP_WAIT0();
        __syncthreads();

        const uint32_t sb = sb0 + (kt % NSTAGE) * STAGE_B;
#pragma unroll
        for (int ks = 0; ks < 2; ks++) {
            const uint32_t kadd = (uint32_t)(ks * 32);
            uint32_t a[4][4], bh[4][2], bl[4][2];
#pragma unroll
            for (int mf = 0; mf < 4; mf++)
                LDSM_X4(a[mf][0], a[mf][1], a[mf][2], a[mf][3],
                        sb + 0 * TILE_B + aoff + kadd + (uint32_t)(mf * 16 * TSTR));
#pragma unroll
            for (int np = 0; np < 2; np++)
                LDSM_X4(bh[np * 2][0], bh[np * 2][1], bh[np * 2 + 1][0], bh[np * 2 + 1][1],
                        sb + 2 * TILE_B + boff + kadd + (uint32_t)(np * 16 * TSTR));
#pragma unroll
            for (int np = 0; np < 2; np++)
                LDSM_X4(bl[np * 2][0], bl[np * 2][1], bl[np * 2 + 1][0], bl[np * 2 + 1][1],
                        sb + 3 * TILE_B + boff + kadd + (uint32_t)(np * 16 * TSTR));
#pragma unroll
            for (int mf = 0; mf < 4; mf++)
#pragma unroll
                for (int nf = 0; nf < 4; nf++) {
                    MMA_BF16(c[mf][nf], a[mf], bh[nf]);
                    MMA_BF16(c[mf][nf], a[mf], bl[nf]);
                }
#pragma unroll
            for (int mf = 0; mf < 4; mf++)
                LDSM_X4(a[mf][0], a[mf][1], a[mf][2], a[mf][3],
                        sb + 1 * TILE_B + aoff + kadd + (uint32_t)(mf * 16 * TSTR));
#pragma unroll
            for (int mf = 0; mf < 4; mf++)
#pragma unroll
                for (int nf = 0; nf < 4; nf++)
                    MMA_BF16(c[mf][nf], a[mf], bh[nf]);
        }
        __syncthreads();
        if (kt + 2 < NK) issue((kt + 2) % NSTAGE, kt + 2);
    }

    const int rb = bm + warpM * 64 + (lane >> 2);
    const int cb = bn + warpN * 32 + (lane & 3) * 2;
#pragma unroll
    for (int mf = 0; mf < 4; mf++) {
#pragma unroll
        for (int nf = 0; nf < 4; nf++) {
            const int col = cb + nf * 8;
            const float b0 = __ldg(&bias[col]);
            const float b1 = __ldg(&bias[col + 1]);
#pragma unroll
            for (int half = 0; half < 2; half++) {
                const int row = rb + mf * 16 + half * 8;
                float v0 = (c[mf][nf][half * 2 + 0] + b0) * scale;
                float v1 = (c[mf][nf][half * 2 + 1] + b1) * scale;
                if (mode == 0) {
                    float2 v; v.x = v0; v.y = v1;
                    *(float2*)&Yf[row * DM + col] = v;
                } else {
                    const int b = row >> 10, t = row & 1023;
                    const int h = col >> 6, d = col & 63;
                    const int dst = ((b * NH + h) * TT + t) * HD + d;
                    float r0, r1;
                    uint32_t hp = pack_hi2(v0, v1, r0, r1);
                    *(uint32_t*)(Yhi + dst) = hp;
                    *(uint32_t*)(Ylo + dst) = pack_bf2(r0, r1);
                }
            }
        }
    }
}

// ---------------------------------------------------------------------------
// K/V projection GEMM, stride-aware: per stride group g (stride = 1<<g),
// compute ONLY rows s = sc*stride for the 4 heads {g, g+4, g+8, g+12}
// (N = 256 remapped weight columns). Output compacted: [b][h][sc][d]
// (row pitch SS kept, rows 0..S_h-1 valid). 46.9% of the dense work.
// grid = (2, 240): blockIdx.y tile ranges [0,128) g0, [128,192) g1,
// [192,224) g2, [224,240) g3.
// ---------------------------------------------------------------------------
__global__ __launch_bounds__(256, 1) void gemm_kv(
    const __nv_bfloat16* __restrict__ Ahi, const __nv_bfloat16* __restrict__ Alo,
    const __nv_bfloat16* __restrict__ Bhi, const __nv_bfloat16* __restrict__ Blo,
    const float* __restrict__ bias,
    __nv_bfloat16* __restrict__ Yhi, __nv_bfloat16* __restrict__ Ylo)
{
    extern __shared__ char dsm[];
    const uint32_t sb0 = (smem_u32(dsm) + 127) & ~127u;

    const int tid = threadIdx.x;
    const int lane = tid & 31;
    const int wid = tid >> 5;
    const int warpM = wid >> 2;
    const int warpN = wid & 3;
    const int bn = blockIdx.x * 128;

    // stride-group decode
    const int ty = blockIdx.y;
    int g, mt;
    if (ty < 128)      { g = 0; mt = ty; }
    else if (ty < 192) { g = 1; mt = ty - 128; }
    else if (ty < 224) { g = 2; mt = ty - 192; }
    else               { g = 3; mt = ty - 224; }
    const int logSh = 12 - g;            // S_h = 4096 >> g
    const int shMask = (1 << logSh) - 1;
    const int bm = mt * 128;             // row index within this group's M

    int gr[2]; uint32_t soff[2];
    long arow[2], brow[2];
#pragma unroll
    for (int i = 0; i < 2; i++) {
        const int id = tid + i * 256;
        gr[i] = id >> 2;
        soff[i] = (uint32_t)(gr[i] * TSTR + (id & 3) * 16);
        // A row: r -> (b, sc) -> encoder row b*SS + sc*stride
        const int r = bm + gr[i];
        const int b = r >> logSh, sc = r & shMask;
        arow[i] = ((long)b * SS + ((long)sc << g)) * DM + (id & 3) * 8;
        // B row: column c -> weight row 64*g + ((c>>6)<<8) + (c&63)
        const int c = bn + gr[i];
        brow[i] = (long)(64 * g + ((c >> 6) << 8) + (c & 63)) * DM + (id & 3) * 8;
    }

    const uint32_t aoff = (uint32_t)((warpM * 64 + (lane & 7) + ((lane >> 3) & 1) * 8) * TSTR
                                     + ((lane >> 4) & 1) * 16);
    const uint32_t boff = (uint32_t)((warpN * 32 + (lane & 7) + ((lane >> 4) & 1) * 8) * TSTR
                                     + ((lane >> 3) & 1) * 16);

    float c[4][4][4];
#pragma unroll
    for (int mf = 0; mf < 4; mf++)
#pragma unroll
        for (int nf = 0; nf < 4; nf++)
#pragma unroll
            for (int k = 0; k < 4; k++) c[mf][nf][k] = 0.0f;

    auto issue = [&](int s, int kc) {
        const uint32_t sb = sb0 + s * STAGE_B;
        const int ko = kc * 32;
#pragma unroll
        for (int i = 0; i < 2; i++) {
            CP_ASYNC16(sb + 0 * TILE_B + soff[i], (const char*)(Ahi + arow[i] + ko));
            CP_ASYNC16(sb + 1 * TILE_B + soff[i], (const char*)(Alo + arow[i] + ko));
            CP_ASYNC16(sb + 2 * TILE_B + soff[i], (const char*)(Bhi + brow[i] + ko));
            CP_ASYNC16(sb + 3 * TILE_B + soff[i], (const char*)(Blo + brow[i] + ko));
        }
        CP_COMMIT();
    };

    issue(0, 0);
    issue(1, 1);

    for (int kt = 0; kt < NK; kt++) {
        if (kt + 1 < NK) CP_WAIT1(); else CP_WAIT0();
        __syncthreads();

        const uint32_t sb = sb0 + (kt % NSTAGE) * STAGE_B;
#pragma unroll
        for (int ks = 0; ks < 2; ks++) {
            const uint32_t kadd = (uint32_t)(ks * 32);
            uint32_t a[4][4], bh[4][2], bl[4][2];
#pragma unroll
            for (int mf = 0; mf < 4; mf++)
                LDSM_X4(a[mf][0], a[mf][1], a[mf][2], a[mf][3],
                        sb + 0 * TILE_B + aoff + kadd + (uint32_t)(mf * 16 * TSTR));
#pragma unroll
            for (int np = 0; np < 2; np++)
                LDSM_X4(bh[np * 2][0], bh[np * 2][1], bh[np * 2 + 1][0], bh[np * 2 + 1][1],
                        sb + 2 * TILE_B + boff + kadd + (uint32_t)(np * 16 * TSTR));
#pragma unroll
            for (int np = 0; np < 2; np++)
                LDSM_X4(bl[np * 2][0], bl[np * 2][1], bl[np * 2 + 1][0], bl[np * 2 + 1][1],
                        sb + 3 * TILE_B + boff + kadd + (uint32_t)(np * 16 * TSTR));
#pragma unroll
            for (int mf = 0; mf < 4; mf++)
#pragma unroll
                for (int nf = 0; nf < 4; nf++) {
                    MMA_BF16(c[mf][nf], a[mf], bh[nf]);
                    MMA_BF16(c[mf][nf], a[mf], bl[nf]);
                }
#pragma unroll
            for (int mf = 0; mf < 4; mf++)
                LDSM_X4(a[mf][0], a[mf][1], a[mf][2], a[mf][3],
                        sb + 1 * TILE_B + aoff + kadd + (uint32_t)(mf * 16 * TSTR));
#pragma unroll
            for (int mf = 0; mf < 4; mf++)
#pragma unroll
                for (int nf = 0; nf < 4; nf++)
                    MMA_BF16(c[mf][nf], a[mf], bh[nf]);
        }
        __syncthreads();
        if (kt + 2 < NK) issue((kt + 2) % NSTAGE, kt + 2);
    }

    // epilogue: compacted head-split scatter
    const int rb = bm + warpM * 64 + (lane >> 2);
    const int cb = bn + warpN * 32 + (lane & 3) * 2;
#pragma unroll
    for (int mf = 0; mf < 4; mf++) {
#pragma unroll
        for (int nf = 0; nf < 4; nf++) {
            const int col = cb + nf * 8;
            const int head = g + ((col >> 6) << 2);
            const int d = col & 63;
            const int wr = head * 64 + d;
            const float b0 = __ldg(&bias[wr]);
            const float b1 = __ldg(&bias[wr + 1]);
#pragma unroll
            for (int half = 0; half < 2; half++) {
                const int row = rb + mf * 16 + half * 8;
                const int b = row >> logSh, sc = row & shMask;
                const int dst = ((b * NH + head) * SS + sc) * HD + d;
                float v0 = c[mf][nf][half * 2 + 0] + b0;
                float v1 = c[mf][nf][half * 2 + 1] + b1;
                float r0, r1;
                uint32_t hp = pack_hi2(v0, v1, r0, r1);
                *(uint32_t*)(Yhi + dst) = hp;
                *(uint32_t*)(Ylo + dst) = pack_bf2(r0, r1);
            }
        }
    }
}

// ---------------------------------------------------------------------------
// Tensor-core flash attention. K/V pre-compacted per head -> contiguous loads.
// ---------------------------------------------------------------------------
#define APITCH 144
#define KVARR (64 * APITCH)
#define ASTG (4 * KVARR)
#define AQ_B (128 * APITCH)
#define ATT_SMEM (2 * AQ_B + 2 * ASTG + 128)

__global__ __launch_bounds__(256, 1) void attn_mma()
{
    extern __shared__ char asm_[];
    const uint32_t sb = (smem_u32(asm_) + 127) & ~127u;
    const uint32_t sQh = sb, sQl = sb + AQ_B;
    const uint32_t sStg = sb + 2 * AQ_B;

    const int tid = threadIdx.x;
    const int lane = tid & 31;
    const int wid = tid >> 5;
    const int qt = blockIdx.x;
    const int h  = blockIdx.y;
    const int b  = blockIdx.z;
    const int nchunk = 64 >> (h & 3);

    const __nv_bfloat16* Qh = g_qhi + ((size_t)(b * NH + h) * TT + qt * 128) * HD;
    const __nv_bfloat16* Ql = g_qlo + ((size_t)(b * NH + h) * TT + qt * 128) * HD;
    const size_t kvbase = (size_t)(b * NH + h) * SS * HD;

    auto issue_kv = [&](int st, int kc) {
        const uint32_t s0 = sStg + st * ASTG;
#pragma unroll
        for (int i = 0; i < 2; i++) {
            const int idx = tid + i * 256;
            const int row = idx >> 3, cc = idx & 7;
            const size_t g = kvbase + (size_t)(kc * 64 + row) * HD + cc * 8;
            const uint32_t d = (uint32_t)(row * APITCH + cc * 16);
            CP_ASYNC16(s0 + 0 * KVARR + d, (const char*)(g_khi + g));
            CP_ASYNC16(s0 + 1 * KVARR + d, (const char*)(g_klo + g));
            CP_ASYNC16(s0 + 2 * KVARR + d, (const char*)(g_vhi + g));
            CP_ASYNC16(s0 + 3 * KVARR + d, (const char*)(g_vlo + g));
        }
        CP_COMMIT();
    };

#pragma unroll
    for (int i = 0; i < 4; i++) {
        const int idx = tid + i * 256;
        const int row = idx >> 3, cc = idx & 7;
        const uint32_t d = (uint32_t)(row * APITCH + cc * 16);
        CP_ASYNC16(sQh + d, (const char*)(Qh + row * HD + cc * 8));
        CP_ASYNC16(sQl + d, (const char*)(Ql + row * HD + cc * 8));
    }
    issue_kv(0, 0);
    issue_kv(1, 1);

    const uint32_t aoff = (uint32_t)((wid * 16 + (lane & 7) + ((lane >> 3) & 1) * 8) * APITCH
                                     + ((lane >> 4) & 1) * 16);
    const uint32_t koff = (uint32_t)(((lane & 7) + ((lane >> 4) & 1) * 8) * APITCH
                                     + ((lane >> 3) & 1) * 16);
    const uint32_t voff = (uint32_t)((lane & 15) * APITCH + (lane >> 4) * 16);

    uint32_t ah[4][4], al[4][4];
    float o[8][4];
#pragma unroll
    for (int nf = 0; nf < 8; nf++)
#pragma unroll
        for (int k = 0; k < 4; k++) o[nf][k] = 0.0f;
    float m0 = -1e30f, m1 = -1e30f, l0 = 0.0f, l1 = 0.0f;

    for (int kc = 0; kc < nchunk; kc++) {
        if (kc + 1 < nchunk) CP_WAIT1(); else CP_WAIT0();
        __syncthreads();

        if (kc == 0) {
#pragma unroll
            for (int ks = 0; ks < 4; ks++) {
                LDSM_X4(ah[ks][0], ah[ks][1], ah[ks][2], ah[ks][3], sQh + aoff + ks * 32);
                LDSM_X4(al[ks][0], al[ks][1], al[ks][2], al[ks][3], sQl + aoff + ks * 32);
            }
        }

        const uint32_t s0 = sStg + (kc & 1) * ASTG;

        float S[8][4];
#pragma unroll
        for (int nf = 0; nf < 8; nf++)
#pragma unroll
            for (int k = 0; k < 4; k++) S[nf][k] = 0.0f;

#pragma unroll
        for (int ks = 0; ks < 4; ks++) {
#pragma unroll
            for (int np = 0; np < 4; np++) {
                uint32_t k0, k1, k2, k3;
                const uint32_t ka = koff + (uint32_t)(np * 16 * APITCH) + ks * 32;
                LDSM_X4(k0, k1, k2, k3, s0 + 0 * KVARR + ka);
                MMA_BF16_2(S[2 * np],     ah[ks], k0, k1);
                MMA_BF16_2(S[2 * np + 1], ah[ks], k2, k3);
                MMA_BF16_2(S[2 * np],     al[ks], k0, k1);
                MMA_BF16_2(S[2 * np + 1], al[ks], k2, k3);
                LDSM_X4(k0, k1, k2, k3, s0 + 1 * KVARR + ka);
                MMA_BF16_2(S[2 * np],     ah[ks], k0, k1);
                MMA_BF16_2(S[2 * np + 1], ah[ks], k2, k3);
            }
        }

        float mx0 = -1e30f, mx1 = -1e30f;
#pragma unroll
        for (int nf = 0; nf < 8; nf++) {
            mx0 = fmaxf(mx0, fmaxf(S[nf][0], S[nf][1]));
            mx1 = fmaxf(mx1, fmaxf(S[nf][2], S[nf][3]));
        }
        mx0 = fmaxf(mx0, __shfl_xor_sync(0xffffffffu, mx0, 1));
        mx0 = fmaxf(mx0, __shfl_xor_sync(0xffffffffu, mx0, 2));
        mx1 = fmaxf(mx1, __shfl_xor_sync(0xffffffffu, mx1, 1));
        mx1 = fmaxf(mx1, __shfl_xor_sync(0xffffffffu, mx1, 2));
        const float mn0 = fmaxf(m0, mx0), mn1 = fmaxf(m1, mx1);
        const float sc0 = ex2f(m0 - mn0), sc1 = ex2f(m1 - mn1);
        m0 = mn0; m1 = mn1;
        l0 *= sc0; l1 *= sc1;
#pragma unroll
        for (int nf = 0; nf < 8; nf++) {
            o[nf][0] *= sc0; o[nf][1] *= sc0;
            o[nf][2] *= sc1; o[nf][3] *= sc1;
        }

        uint32_t ph[4][4], pl[4][4];
#pragma unroll
        for (int nf = 0; nf < 8; nf++) {
            const float p0 = ex2f(S[nf][0] - mn0);
            const float p1 = ex2f(S[nf][1] - mn0);
            const float p2 = ex2f(S[nf][2] - mn1);
            const float p3 = ex2f(S[nf][3] - mn1);
            l0 += p0 + p1; l1 += p2 + p3;
            const int ks = nf >> 1, sl = (nf & 1) * 2;
            float r0, r1, r2, r3;
            ph[ks][sl + 0] = pack_hi2(p0, p1, r0, r1);
            ph[ks][sl + 1] = pack_hi2(p2, p3, r2, r3);
            pl[ks][sl + 0] = pack_bf2(r0, r1);
            pl[ks][sl + 1] = pack_bf2(r2, r3);
        }

#pragma unroll
        for (int ks = 0; ks < 4; ks++) {
#pragma unroll
            for (int nd = 0; nd < 4; nd++) {
                uint32_t v0, v1, v2, v3;
                const uint32_t va = voff + (uint32_t)(ks * 16 * APITCH) + (uint32_t)(nd * 32);
                LDSM_X4_T(v0, v1, v2, v3, s0 + 2 * KVARR + va);
                MMA_BF16_2(o[2 * nd],     ph[ks], v0, v1);
                MMA_BF16_2(o[2 * nd + 1], ph[ks], v2, v3);
                MMA_BF16_2(o[2 * nd],     pl[ks], v0, v1);
                MMA_BF16_2(o[2 * nd + 1], pl[ks], v2, v3);
                LDSM_X4_T(v0, v1, v2, v3, s0 + 3 * KVARR + va);
                MMA_BF16_2(o[2 * nd],     ph[ks], v0, v1);
                MMA_BF16_2(o[2 * nd + 1], ph[ks], v2, v3);
            }
        }

        __syncthreads();
        if (kc + 2 < nchunk) issue_kv(kc & 1, kc + 2);
    }

    l0 += __shfl_xor_sync(0xffffffffu, l0, 1);
    l0 += __shfl_xor_sync(0xffffffffu, l0, 2);
    l1 += __shfl_xor_sync(0xffffffffu, l1, 1);
    l1 += __shfl_xor_sync(0xffffffffu, l1, 2);
    const float inv0 = 1.0f / l0, inv1 = 1.0f / l1;
    const int t0 = qt * 128 + wid * 16 + (lane >> 2);
    const size_t base0 = (size_t)(b * TT + t0) * DM + h * HD;
    const size_t base1 = base0 + 8 * DM;
#pragma unroll
    for (int nf = 0; nf < 8; nf++) {
        const int d = nf * 8 + (lane & 3) * 2;
        float r0, r1;
        uint32_t hp = pack_hi2(o[nf][0] * inv0, o[nf][1] * inv0, r0, r1);
        *(uint32_t*)(g_atthi + base0 + d) = hp;
        *(uint32_t*)(g_attlo + base0 + d) = pack_bf2(r0, r1);
        hp = pack_hi2(o[nf][2] * inv1, o[nf][3] * inv1, r0, r1);
        *(uint32_t*)(g_atthi + base1 + d) = hp;
        *(uint32_t*)(g_attlo + base1 + d) = pack_bf2(r0, r1);
    }
}

// ---------------------------------------------------------------------------
extern "C" void kernel_launch(void* const* d_in, const int* in_sizes, int n_in,
                              void* d_out, int out_size)
{
    const float* dec = (const float*)d_in[0];
    const float* enc = (const float*)d_in[1];
    const float* Wq  = (const float*)d_in[2];
    const float* bq  = (const float*)d_in[3];
    const float* Wk  = (const float*)d_in[4];
    const float* bk  = (const float*)d_in[5];
    const float* Wv  = (const float*)d_in[6];
    const float* bv  = (const float*)d_in[7];
    const float* Wo  = (const float*)d_in[8];
    const float* bo  = (const float*)d_in[9];

    __nv_bfloat16 *qh_, *ql_, *kh_, *kl_, *vh_, *vl_;
    cudaGetSymbolAddress((void**)&qh_, g_qhi);  cudaGetSymbolAddress((void**)&ql_, g_qlo);
    cudaGetSymbolAddress((void**)&kh_, g_khi);  cudaGetSymbolAddress((void**)&kl_, g_klo);
    cudaGetSymbolAddress((void**)&vh_, g_vhi);  cudaGetSymbolAddress((void**)&vl_, g_vlo);
    __nv_bfloat16 *dh, *dl, *eh, *el, *wqh, *wql, *wkh, *wkl, *wvh, *wvl, *woh, *wol, *ah, *al;
    cudaGetSymbolAddress((void**)&dh, g_dechi);  cudaGetSymbolAddress((void**)&dl, g_declo);
    cudaGetSymbolAddress((void**)&eh, g_enchi);  cudaGetSymbolAddress((void**)&el, g_enclo);
    cudaGetSymbolAddress((void**)&wqh, g_wqhi);  cudaGetSymbolAddress((void**)&wql, g_wqlo);
    cudaGetSymbolAddress((void**)&wkh, g_wkhi);  cudaGetSymbolAddress((void**)&wkl, g_wklo);
    cudaGetSymbolAddress((void**)&wvh, g_wvhi);  cudaGetSymbolAddress((void**)&wvl, g_wvlo);
    cudaGetSymbolAddress((void**)&woh, g_wohi);  cudaGetSymbolAddress((void**)&wol, g_wolo);
    cudaGetSymbolAddress((void**)&ah, g_atthi);  cudaGetSymbolAddress((void**)&al, g_attlo);

    cudaFuncSetAttribute((const void*)gemm_mma,
                         cudaFuncAttributeMaxDynamicSharedMemorySize, GEMM_SMEM);
    cudaFuncSetAttribute((const void*)gemm_kv,
                         cudaFuncAttributeMaxDynamicSharedMemorySize, GEMM_SMEM);
    cudaFuncSetAttribute((const void*)attn_mma,
                         cudaFuncAttributeMaxDynamicSharedMemorySize, ATT_SMEM);

    split_kernel<<<(BB * TT * DM / 4 + 255) / 256, 256>>>(dec, dh, dl, BB * TT * DM / 4);
    split_kernel<<<(BB * SS * DM / 4 + 255) / 256, 256>>>(enc, eh, el, BB * SS * DM / 4);
    split_kernel<<<(DM * DM / 4 + 255) / 256, 256>>>(Wq, wqh, wql, DM * DM / 4);
    split_kernel<<<(DM * DM / 4 + 255) / 256, 256>>>(Wk, wkh, wkl, DM * DM / 4);
    split_kernel<<<(DM * DM / 4 + 255) / 256, 256>>>(Wv, wvh, wvl, DM * DM / 4);
    split_kernel<<<(DM * DM / 4 + 255) / 256, 256>>>(Wo, woh, wol, DM * DM / 4);

    gemm_mma<<<dim3(8, 32), 256, GEMM_SMEM>>>(dh, dl, wqh, wql, bq,
                                              nullptr, qh_, ql_, SCALE_Q, 1);
    gemm_kv<<<dim3(2, 240), 256, GEMM_SMEM>>>(eh, el, wkh, wkl, bk, kh_, kl_);
    gemm_kv<<<dim3(2, 240), 256, GEMM_SMEM>>>(eh, el, wvh, wvl, bv, vh_, vl_);

    attn_mma<<<dim3(TT / 128, NH, BB), 256, ATT_SMEM>>>();

    gemm_mma<<<dim3(8, 32), 256, GEMM_SMEM>>>(ah, al, woh, wol, bo,
                                              (float*)d_out, nullptr, nullptr, 1.0f, 0);
}

// round 8
// speedup vs baseline: 6.9835x; 2.1098x over previous
#include <cuda_runtime.h>
#include <cuda_fp16.h>
#include <math.h>
#include <stdint.h>

#define DM 1024
#define NH 16
#define HD 64
#define BB 4
#define TT 1024
#define SS 4096

#define SCALE_Q 0.1803368801111204f   // 0.125 * log2(e)

// ---------------- scratch (__device__ globals) ------------------------------
__device__ __half g_q[BB * NH * TT * HD];
__device__ __half g_k[BB * NH * SS * HD];
__device__ __half g_v[BB * NH * SS * HD];

__device__ __half g_dec[BB * TT * DM];
__device__ __half g_enc[BB * SS * DM];
__device__ __half g_wq[DM * DM], g_wk[DM * DM], g_wv[DM * DM], g_wo[DM * DM];
__device__ __half g_att[BB * TT * DM];

// ---------------- helpers ---------------------------------------------------
__device__ __forceinline__ uint32_t smem_u32(const void* p) {
    uint32_t a;
    asm("{ .reg .u64 t; cvta.to.shared.u64 t, %1; cvt.u32.u64 %0, t; }"
        : "=r"(a) : "l"(p));
    return a;
}
__device__ __forceinline__ float ex2f(float x) {
    float y;
    asm("ex2.approx.ftz.f32 %0, %1;" : "=f"(y) : "f"(x));
    return y;
}
__device__ __forceinline__ uint32_t packh2(float a, float b) {
    __half2 t = __floats2half2_rn(a, b);
    return *(uint32_t*)&t;
}

#define CP_ASYNC16(sa, ga) \
    asm volatile("cp.async.cg.shared.global [%0], [%1], 16;" :: "r"(sa), "l"(ga))
#define CP_COMMIT() asm volatile("cp.async.commit_group;" ::: "memory")
#define CP_WAIT2()  asm volatile("cp.async.wait_group 2;" ::: "memory")
#define CP_WAIT1()  asm volatile("cp.async.wait_group 1;" ::: "memory")
#define CP_WAIT0()  asm volatile("cp.async.wait_group 0;" ::: "memory")

#define LDSM_X4(r0, r1, r2, r3, a) \
    asm volatile("ldmatrix.sync.aligned.m8n8.x4.shared.b16 {%0,%1,%2,%3}, [%4];" \
                 : "=r"(r0), "=r"(r1), "=r"(r2), "=r"(r3) : "r"(a))
#define LDSM_X4_T(r0, r1, r2, r3, a) \
    asm volatile("ldmatrix.sync.aligned.m8n8.x4.trans.shared.b16 {%0,%1,%2,%3}, [%4];" \
                 : "=r"(r0), "=r"(r1), "=r"(r2), "=r"(r3) : "r"(a))

#define MMA_F16(c, a, b) \
    asm volatile("mma.sync.aligned.m16n8k16.row.col.f32.f16.f16.f32 " \
                 "{%0,%1,%2,%3}, {%4,%5,%6,%7}, {%8,%9}, {%0,%1,%2,%3};" \
                 : "+f"((c)[0]), "+f"((c)[1]), "+f"((c)[2]), "+f"((c)[3]) \
                 : "r"((a)[0]), "r"((a)[1]), "r"((a)[2]), "r"((a)[3]), \
                   "r"((b)[0]), "r"((b)[1]))
#define MMA_F16_2(c, a, b0, b1) \
    asm volatile("mma.sync.aligned.m16n8k16.row.col.f32.f16.f16.f32 " \
                 "{%0,%1,%2,%3}, {%4,%5,%6,%7}, {%8,%9}, {%0,%1,%2,%3};" \
                 : "+f"((c)[0]), "+f"((c)[1]), "+f"((c)[2]), "+f"((c)[3]) \
                 : "r"((a)[0]), "r"((a)[1]), "r"((a)[2]), "r"((a)[3]), \
                   "r"(b0), "r"(b1))

// ---------------------------------------------------------------------------
// fp32 -> fp16 convert (8 elems/thread)
// ---------------------------------------------------------------------------
__global__ void cvt_kernel(const float* __restrict__ src,
                           __half* __restrict__ dst, int n8)
{
    int i = blockIdx.x * blockDim.x + threadIdx.x;
    if (i >= n8) return;
    float4 a = ((const float4*)src)[2 * i];
    float4 b = ((const float4*)src)[2 * i + 1];
    uint4 o;
    o.x = packh2(a.x, a.y);
    o.y = packh2(a.z, a.w);
    o.z = packh2(b.x, b.y);
    o.w = packh2(b.z, b.w);
    ((uint4*)dst)[i] = o;
}

// ---------------------------------------------------------------------------
// fp16 mma.sync GEMM (dense):  Y = (A @ B^T + bias) * scale
// mode 0: fp32 out plain [row][col]; mode 1: Q head-split fp16 (scaled).
// CTA 128x128, 8 warps (2Mx4N), k-chunk 32, 4-stage cp.async pipeline.
// ---------------------------------------------------------------------------
#define TSTR 80                    // 64 B data + 16 pad
#define TILE_B (128 * TSTR)        // 10240
#define STAGE_B (2 * TILE_B)       // A|B = 20480
#define NSTAGE 4
#define GEMM_SMEM (NSTAGE * STAGE_B + 128)
#define NK 32

__global__ __launch_bounds__(256, 1) void gemm_mma(
    const __half* __restrict__ A, const __half* __restrict__ B,
    const float* __restrict__ bias, float* __restrict__ Yf,
    __half* __restrict__ Yh, float scale, int mode)
{
    extern __shared__ char dsm[];
    const uint32_t sb0 = (smem_u32(dsm) + 127) & ~127u;

    const int tid = threadIdx.x;
    const int lane = tid & 31;
    const int wid = tid >> 5;
    const int warpM = wid >> 2;
    const int warpN = wid & 3;
    const int bn = blockIdx.x * 128;
    const int bm = blockIdx.y * 128;

    int gr[2], gc[2]; uint32_t soff[2];
#pragma unroll
    for (int i = 0; i < 2; i++) {
        const int id = tid + i * 256;
        gr[i] = id >> 2;
        gc[i] = (id & 3) * 8;
        soff[i] = (uint32_t)(gr[i] * TSTR + (id & 3) * 16);
    }

    const uint32_t aoff = (uint32_t)((warpM * 64 + (lane & 7) + ((lane >> 3) & 1) * 8) * TSTR
                                     + ((lane >> 4) & 1) * 16);
    const uint32_t boff = (uint32_t)((warpN * 32 + (lane & 7) + ((lane >> 4) & 1) * 8) * TSTR
                                     + ((lane >> 3) & 1) * 16);

    float c[4][4][4];
#pragma unroll
    for (int mf = 0; mf < 4; mf++)
#pragma unroll
        for (int nf = 0; nf < 4; nf++)
#pragma unroll
            for (int k = 0; k < 4; k++) c[mf][nf][k] = 0.0f;

    auto issue = [&](int s, int kc) {
        const uint32_t sb = sb0 + s * STAGE_B;
        const int ko = kc * 32;
#pragma unroll
        for (int i = 0; i < 2; i++) {
            const long ag = (long)(bm + gr[i]) * DM + ko + gc[i];
            const long bg = (long)(bn + gr[i]) * DM + ko + gc[i];
            CP_ASYNC16(sb + 0 * TILE_B + soff[i], (const char*)(A + ag));
            CP_ASYNC16(sb + 1 * TILE_B + soff[i], (const char*)(B + bg));
        }
        CP_COMMIT();
    };

    issue(0, 0); issue(1, 1); issue(2, 2);

    for (int kt = 0; kt < NK; kt++) {
        if (kt + 2 < NK) CP_WAIT2();
        else if (kt + 1 < NK) CP_WAIT1();
        else CP_WAIT0();
        __syncthreads();

        const uint32_t sb = sb0 + (kt % NSTAGE) * STAGE_B;
#pragma unroll
        for (int ks = 0; ks < 2; ks++) {
            const uint32_t kadd = (uint32_t)(ks * 32);
            uint32_t a[4][4], bfr[4][2];
#pragma unroll
            for (int mf = 0; mf < 4; mf++)
                LDSM_X4(a[mf][0], a[mf][1], a[mf][2], a[mf][3],
                        sb + 0 * TILE_B + aoff + kadd + (uint32_t)(mf * 16 * TSTR));
#pragma unroll
            for (int np = 0; np < 2; np++)
                LDSM_X4(bfr[np * 2][0], bfr[np * 2][1], bfr[np * 2 + 1][0], bfr[np * 2 + 1][1],
                        sb + 1 * TILE_B + boff + kadd + (uint32_t)(np * 16 * TSTR));
#pragma unroll
            for (int mf = 0; mf < 4; mf++)
#pragma unroll
                for (int nf = 0; nf < 4; nf++)
                    MMA_F16(c[mf][nf], a[mf], bfr[nf]);
        }
        __syncthreads();
        if (kt + 3 < NK) issue((kt + 3) % NSTAGE, kt + 3);
    }

    const int rb = bm + warpM * 64 + (lane >> 2);
    const int cb = bn + warpN * 32 + (lane & 3) * 2;
#pragma unroll
    for (int mf = 0; mf < 4; mf++) {
#pragma unroll
        for (int nf = 0; nf < 4; nf++) {
            const int col = cb + nf * 8;
            const float b0 = __ldg(&bias[col]);
            const float b1 = __ldg(&bias[col + 1]);
#pragma unroll
            for (int half = 0; half < 2; half++) {
                const int row = rb + mf * 16 + half * 8;
                float v0 = (c[mf][nf][half * 2 + 0] + b0) * scale;
                float v1 = (c[mf][nf][half * 2 + 1] + b1) * scale;
                if (mode == 0) {
                    float2 v; v.x = v0; v.y = v1;
                    *(float2*)&Yf[row * DM + col] = v;
                } else {
                    const int b = row >> 10, t = row & 1023;
                    const int h = col >> 6, d = col & 63;
                    const int dst = ((b * NH + h) * TT + t) * HD + d;
                    *(uint32_t*)(Yh + dst) = packh2(v0, v1);
                }
            }
        }
    }
}

// ---------------------------------------------------------------------------
// K/V projection GEMM, stride-aware (46.9% of dense work), fp16 single-pass.
// grid (2, 240): y in [0,128) g0, [128,192) g1, [192,224) g2, [224,240) g3.
// Output compacted per head: [b][h][sc][d], row pitch SS.
// ---------------------------------------------------------------------------
__global__ __launch_bounds__(256, 1) void gemm_kv(
    const __half* __restrict__ A, const __half* __restrict__ B,
    const float* __restrict__ bias, __half* __restrict__ Yh)
{
    extern __shared__ char dsm[];
    const uint32_t sb0 = (smem_u32(dsm) + 127) & ~127u;

    const int tid = threadIdx.x;
    const int lane = tid & 31;
    const int wid = tid >> 5;
    const int warpM = wid >> 2;
    const int warpN = wid & 3;
    const int bn = blockIdx.x * 128;

    const int ty = blockIdx.y;
    int g, mt;
    if (ty < 128)      { g = 0; mt = ty; }
    else if (ty < 192) { g = 1; mt = ty - 128; }
    else if (ty < 224) { g = 2; mt = ty - 192; }
    else               { g = 3; mt = ty - 224; }
    const int logSh = 12 - g;
    const int shMask = (1 << logSh) - 1;
    const int bm = mt * 128;

    uint32_t soff[2];
    long arow[2], brow[2];
#pragma unroll
    for (int i = 0; i < 2; i++) {
        const int id = tid + i * 256;
        const int r0 = id >> 2;
        soff[i] = (uint32_t)(r0 * TSTR + (id & 3) * 16);
        const int r = bm + r0;
        const int b = r >> logSh, sc = r & shMask;
        arow[i] = ((long)b * SS + ((long)sc << g)) * DM + (id & 3) * 8;
        const int cc = bn + r0;
        brow[i] = (long)(64 * g + ((cc >> 6) << 8) + (cc & 63)) * DM + (id & 3) * 8;
    }

    const uint32_t aoff = (uint32_t)((warpM * 64 + (lane & 7) + ((lane >> 3) & 1) * 8) * TSTR
                                     + ((lane >> 4) & 1) * 16);
    const uint32_t boff = (uint32_t)((warpN * 32 + (lane & 7) + ((lane >> 4) & 1) * 8) * TSTR
                                     + ((lane >> 3) & 1) * 16);

    float c[4][4][4];
#pragma unroll
    for (int mf = 0; mf < 4; mf++)
#pragma unroll
        for (int nf = 0; nf < 4; nf++)
#pragma unroll
            for (int k = 0; k < 4; k++) c[mf][nf][k] = 0.0f;

    auto issue = [&](int s, int kc) {
        const uint32_t sb = sb0 + s * STAGE_B;
        const int ko = kc * 32;
#pragma unroll
        for (int i = 0; i < 2; i++) {
            CP_ASYNC16(sb + 0 * TILE_B + soff[i], (const char*)(A + arow[i] + ko));
            CP_ASYNC16(sb + 1 * TILE_B + soff[i], (const char*)(B + brow[i] + ko));
        }
        CP_COMMIT();
    };

    issue(0, 0); issue(1, 1); issue(2, 2);

    for (int kt = 0; kt < NK; kt++) {
        if (kt + 2 < NK) CP_WAIT2();
        else if (kt + 1 < NK) CP_WAIT1();
        else CP_WAIT0();
        __syncthreads();

        const uint32_t sb = sb0 + (kt % NSTAGE) * STAGE_B;
#pragma unroll
        for (int ks = 0; ks < 2; ks++) {
            const uint32_t kadd = (uint32_t)(ks * 32);
            uint32_t a[4][4], bfr[4][2];
#pragma unroll
            for (int mf = 0; mf < 4; mf++)
                LDSM_X4(a[mf][0], a[mf][1], a[mf][2], a[mf][3],
                        sb + 0 * TILE_B + aoff + kadd + (uint32_t)(mf * 16 * TSTR));
#pragma unroll
            for (int np = 0; np < 2; np++)
                LDSM_X4(bfr[np * 2][0], bfr[np * 2][1], bfr[np * 2 + 1][0], bfr[np * 2 + 1][1],
                        sb + 1 * TILE_B + boff + kadd + (uint32_t)(np * 16 * TSTR));
#pragma unroll
            for (int mf = 0; mf < 4; mf++)
#pragma unroll
                for (int nf = 0; nf < 4; nf++)
                    MMA_F16(c[mf][nf], a[mf], bfr[nf]);
        }
        __syncthreads();
        if (kt + 3 < NK) issue((kt + 3) % NSTAGE, kt + 3);
    }

    const int rb = bm + warpM * 64 + (lane >> 2);
    const int cb = bn + warpN * 32 + (lane & 3) * 2;
#pragma unroll
    for (int mf = 0; mf < 4; mf++) {
#pragma unroll
        for (int nf = 0; nf < 4; nf++) {
            const int col = cb + nf * 8;
            const int head = g + ((col >> 6) << 2);
            const int d = col & 63;
            const int wr = head * 64 + d;
            const float b0 = __ldg(&bias[wr]);
            const float b1 = __ldg(&bias[wr + 1]);
#pragma unroll
            for (int half = 0; half < 2; half++) {
                const int row = rb + mf * 16 + half * 8;
                const int b = row >> logSh, sc = row & shMask;
                const int dst = ((b * NH + head) * SS + sc) * HD + d;
                *(uint32_t*)(Yh + dst) = packh2(c[mf][nf][half * 2 + 0] + b0,
                                                c[mf][nf][half * 2 + 1] + b1);
            }
        }
    }
}

// ---------------------------------------------------------------------------
// fp16 tensor-core flash attention; K/V pre-compacted -> contiguous loads.
// CTA: 128 q-rows (8 warps x m16), 64-key chunks, double-buffered K/V.
// ---------------------------------------------------------------------------
#define APITCH 144
#define KVARR (64 * APITCH)        // 9216 per tile
#define ASTG (2 * KVARR)           // K|V = 18432
#define AQ_B (128 * APITCH)        // 18432
#define ATT_SMEM (AQ_B + 2 * ASTG + 128)

__global__ __launch_bounds__(256, 1) void attn_mma()
{
    extern __shared__ char asm_[];
    const uint32_t sb = (smem_u32(asm_) + 127) & ~127u;
    const uint32_t sQ = sb;
    const uint32_t sStg = sb + AQ_B;

    const int tid = threadIdx.x;
    const int lane = tid & 31;
    const int wid = tid >> 5;
    const int qt = blockIdx.x;
    const int h  = blockIdx.y;
    const int b  = blockIdx.z;
    const int nchunk = 64 >> (h & 3);

    const __half* Qg = g_q + ((size_t)(b * NH + h) * TT + qt * 128) * HD;
    const size_t kvbase = (size_t)(b * NH + h) * SS * HD;

    auto issue_kv = [&](int st, int kc) {
        const uint32_t s0 = sStg + st * ASTG;
#pragma unroll
        for (int i = 0; i < 2; i++) {
            const int idx = tid + i * 256;
            const int row = idx >> 3, cc = idx & 7;
            const size_t g = kvbase + (size_t)(kc * 64 + row) * HD + cc * 8;
            const uint32_t d = (uint32_t)(row * APITCH + cc * 16);
            CP_ASYNC16(s0 + 0 * KVARR + d, (const char*)(g_k + g));
            CP_ASYNC16(s0 + 1 * KVARR + d, (const char*)(g_v + g));
        }
        CP_COMMIT();
    };

#pragma unroll
    for (int i = 0; i < 4; i++) {
        const int idx = tid + i * 256;
        const int row = idx >> 3, cc = idx & 7;
        const uint32_t d = (uint32_t)(row * APITCH + cc * 16);
        CP_ASYNC16(sQ + d, (const char*)(Qg + row * HD + cc * 8));
    }
    issue_kv(0, 0);
    issue_kv(1, 1);

    const uint32_t aoff = (uint32_t)((wid * 16 + (lane & 7) + ((lane >> 3) & 1) * 8) * APITCH
                                     + ((lane >> 4) & 1) * 16);
    const uint32_t koff = (uint32_t)(((lane & 7) + ((lane >> 4) & 1) * 8) * APITCH
                                     + ((lane >> 3) & 1) * 16);
    const uint32_t voff = (uint32_t)((lane & 15) * APITCH + (lane >> 4) * 16);

    uint32_t ah[4][4];
    float o[8][4];
#pragma unroll
    for (int nf = 0; nf < 8; nf++)
#pragma unroll
        for (int k = 0; k < 4; k++) o[nf][k] = 0.0f;
    float m0 = -1e30f, m1 = -1e30f, l0 = 0.0f, l1 = 0.0f;

    for (int kc = 0; kc < nchunk; kc++) {
        if (kc + 1 < nchunk) CP_WAIT1(); else CP_WAIT0();
        __syncthreads();

        if (kc == 0) {
#pragma unroll
            for (int ks = 0; ks < 4; ks++)
                LDSM_X4(ah[ks][0], ah[ks][1], ah[ks][2], ah[ks][3], sQ + aoff + ks * 32);
        }

        const uint32_t s0 = sStg + (kc & 1) * ASTG;

        float S[8][4];
#pragma unroll
        for (int nf = 0; nf < 8; nf++)
#pragma unroll
            for (int k = 0; k < 4; k++) S[nf][k] = 0.0f;

#pragma unroll
        for (int ks = 0; ks < 4; ks++) {
#pragma unroll
            for (int np = 0; np < 4; np++) {
                uint32_t k0, k1, k2, k3;
                const uint32_t ka = koff + (uint32_t)(np * 16 * APITCH) + ks * 32;
                LDSM_X4(k0, k1, k2, k3, s0 + 0 * KVARR + ka);
                MMA_F16_2(S[2 * np],     ah[ks], k0, k1);
                MMA_F16_2(S[2 * np + 1], ah[ks], k2, k3);
            }
        }

        float mx0 = -1e30f, mx1 = -1e30f;
#pragma unroll
        for (int nf = 0; nf < 8; nf++) {
            mx0 = fmaxf(mx0, fmaxf(S[nf][0], S[nf][1]));
            mx1 = fmaxf(mx1, fmaxf(S[nf][2], S[nf][3]));
        }
        mx0 = fmaxf(mx0, __shfl_xor_sync(0xffffffffu, mx0, 1));
        mx0 = fmaxf(mx0, __shfl_xor_sync(0xffffffffu, mx0, 2));
        mx1 = fmaxf(mx1, __shfl_xor_sync(0xffffffffu, mx1, 1));
        mx1 = fmaxf(mx1, __shfl_xor_sync(0xffffffffu, mx1, 2));
        const float mn0 = fmaxf(m0, mx0), mn1 = fmaxf(m1, mx1);
        const float sc0 = ex2f(m0 - mn0), sc1 = ex2f(m1 - mn1);
        m0 = mn0; m1 = mn1;
        l0 *= sc0; l1 *= sc1;
#pragma unroll
        for (int nf = 0; nf < 8; nf++) {
            o[nf][0] *= sc0; o[nf][1] *= sc0;
            o[nf][2] *= sc1; o[nf][3] *= sc1;
        }

        uint32_t ph[4][4];
#pragma unroll
        for (int nf = 0; nf < 8; nf++) {
            const float p0 = ex2f(S[nf][0] - mn0);
            const float p1 = ex2f(S[nf][1] - mn0);
            const float p2 = ex2f(S[nf][2] - mn1);
            const float p3 = ex2f(S[nf][3] - mn1);
            l0 += p0 + p1; l1 += p2 + p3;
            const int ks = nf >> 1, sl = (nf & 1) * 2;
            ph[ks][sl + 0] = packh2(p0, p1);
            ph[ks][sl + 1] = packh2(p2, p3);
        }

#pragma unroll
        for (int ks = 0; ks < 4; ks++) {
#pragma unroll
            for (int nd = 0; nd < 4; nd++) {
                uint32_t v0, v1, v2, v3;
                const uint32_t va = voff + (uint32_t)(ks * 16 * APITCH) + (uint32_t)(nd * 32);
                LDSM_X4_T(v0, v1, v2, v3, s0 + 1 * KVARR + va);
                MMA_F16_2(o[2 * nd],     ph[ks], v0, v1);
                MMA_F16_2(o[2 * nd + 1], ph[ks], v2, v3);
            }
        }

        __syncthreads();
        if (kc + 2 < nchunk) issue_kv(kc & 1, kc + 2);
    }

    l0 += __shfl_xor_sync(0xffffffffu, l0, 1);
    l0 += __shfl_xor_sync(0xffffffffu, l0, 2);
    l1 += __shfl_xor_sync(0xffffffffu, l1, 1);
    l1 += __shfl_xor_sync(0xffffffffu, l1, 2);
    const float inv0 = 1.0f / l0, inv1 = 1.0f / l1;
    const int t0 = qt * 128 + wid * 16 + (lane >> 2);
    const size_t base0 = (size_t)(b * TT + t0) * DM + h * HD;
    const size_t base1 = base0 + 8 * DM;
#pragma unroll
    for (int nf = 0; nf < 8; nf++) {
        const int d = nf * 8 + (lane & 3) * 2;
        *(uint32_t*)(g_att + base0 + d) = packh2(o[nf][0] * inv0, o[nf][1] * inv0);
        *(uint32_t*)(g_att + base1 + d) = packh2(o[nf][2] * inv1, o[nf][3] * inv1);
    }
}

// ---------------------------------------------------------------------------
extern "C" void kernel_launch(void* const* d_in, const int* in_sizes, int n_in,
                              void* d_out, int out_size)
{
    const float* dec = (const float*)d_in[0];
    const float* enc = (const float*)d_in[1];
    const float* Wq  = (const float*)d_in[2];
    const float* bq  = (const float*)d_in[3];
    const float* Wk  = (const float*)d_in[4];
    const float* bk  = (const float*)d_in[5];
    const float* Wv  = (const float*)d_in[6];
    const float* bv  = (const float*)d_in[7];
    const float* Wo  = (const float*)d_in[8];
    const float* bo  = (const float*)d_in[9];

    __half *q_, *k_, *v_, *dec_, *enc_, *wq_, *wk_, *wv_, *wo_, *att_;
    cudaGetSymbolAddress((void**)&q_, g_q);
    cudaGetSymbolAddress((void**)&k_, g_k);
    cudaGetSymbolAddress((void**)&v_, g_v);
    cudaGetSymbolAddress((void**)&dec_, g_dec);
    cudaGetSymbolAddress((void**)&enc_, g_enc);
    cudaGetSymbolAddress((void**)&wq_, g_wq);
    cudaGetSymbolAddress((void**)&wk_, g_wk);
    cudaGetSymbolAddress((void**)&wv_, g_wv);
    cudaGetSymbolAddress((void**)&wo_, g_wo);
    cudaGetSymbolAddress((void**)&att_, g_att);

    cudaFuncSetAttribute((const void*)gemm_mma,
                         cudaFuncAttributeMaxDynamicSharedMemorySize, GEMM_SMEM);
    cudaFuncSetAttribute((const void*)gemm_kv,
                         cudaFuncAttributeMaxDynamicSharedMemorySize, GEMM_SMEM);
    cudaFuncSetAttribute((const void*)attn_mma,
                         cudaFuncAttributeMaxDynamicSharedMemorySize, ATT_SMEM);

    cvt_kernel<<<BB * TT * DM / 8 / 256, 256>>>(dec, dec_, BB * TT * DM / 8);
    cvt_kernel<<<BB * SS * DM / 8 / 256, 256>>>(enc, enc_, BB * SS * DM / 8);
    cvt_kernel<<<DM * DM / 8 / 256, 256>>>(Wq, wq_, DM * DM / 8);
    cvt_kernel<<<DM * DM / 8 / 256, 256>>>(Wk, wk_, DM * DM / 8);
    cvt_kernel<<<DM * DM / 8 / 256, 256>>>(Wv, wv_, DM * DM / 8);
    cvt_kernel<<<DM * DM / 8 / 256, 256>>>(Wo, wo_, DM * DM / 8);

    gemm_mma<<<dim3(8, 32), 256, GEMM_SMEM>>>(dec_, wq_, bq, nullptr, q_, SCALE_Q, 1);
    gemm_kv<<<dim3(2, 240), 256, GEMM_SMEM>>>(enc_, wk_, bk, k_);
    gemm_kv<<<dim3(2, 240), 256, GEMM_SMEM>>>(enc_, wv_, bv, v_);

    attn_mma<<<dim3(TT / 128, NH, BB), 256, ATT_SMEM>>>();

    gemm_mma<<<dim3(8, 32), 256, GEMM_SMEM>>>(att_, wo_, bo, (float*)d_out, nullptr, 1.0f, 0);
}

// round 11
// speedup vs baseline: 7.2962x; 1.0448x over previous
#include <cuda_runtime.h>
#include <cuda_fp16.h>
#include <math.h>
#include <stdint.h>

#define DM 1024
#define NH 16
#define HD 64
#define BB 4
#define TT 1024
#define SS 4096

#define SCALE_Q 0.1803368801111204f   // 0.125 * log2(e)

// ---------------- scratch (__device__ globals) ------------------------------
__device__ __half g_q[BB * NH * TT * HD];
__device__ __half g_k[BB * NH * SS * HD];
__device__ __half g_v[BB * NH * SS * HD];

__device__ __half g_dec[BB * TT * DM];
__device__ __half g_enc[BB * SS * DM];
__device__ __half g_wq[DM * DM], g_wk[DM * DM], g_wv[DM * DM], g_wo[DM * DM];
__device__ __half g_att[BB * TT * DM];

// ---------------- helpers ---------------------------------------------------
__device__ __forceinline__ uint32_t smem_u32(const void* p) {
    uint32_t a;
    asm("{ .reg .u64 t; cvta.to.shared.u64 t, %1; cvt.u32.u64 %0, t; }"
        : "=r"(a) : "l"(p));
    return a;
}
__device__ __forceinline__ float ex2f(float x) {
    float y;
    asm("ex2.approx.ftz.f32 %0, %1;" : "=f"(y) : "f"(x));
    return y;
}
__device__ __forceinline__ uint32_t packh2(float a, float b) {
    __half2 t = __floats2half2_rn(a, b);
    return *(uint32_t*)&t;
}

#define CP_ASYNC16(sa, ga) \
    asm volatile("cp.async.cg.shared.global [%0], [%1], 16;" :: "r"(sa), "l"(ga))
#define CP_COMMIT() asm volatile("cp.async.commit_group;" ::: "memory")
#define CP_WAIT1()  asm volatile("cp.async.wait_group 1;" ::: "memory")
#define CP_WAIT0()  asm volatile("cp.async.wait_group 0;" ::: "memory")

#define LDSM_X4(r0, r1, r2, r3, a) \
    asm volatile("ldmatrix.sync.aligned.m8n8.x4.shared.b16 {%0,%1,%2,%3}, [%4];" \
                 : "=r"(r0), "=r"(r1), "=r"(r2), "=r"(r3) : "r"(a))
#define LDSM_X4_T(r0, r1, r2, r3, a) \
    asm volatile("ldmatrix.sync.aligned.m8n8.x4.trans.shared.b16 {%0,%1,%2,%3}, [%4];" \
                 : "=r"(r0), "=r"(r1), "=r"(r2), "=r"(r3) : "r"(a))

#define MMA_F16(c, a, b) \
    asm volatile("mma.sync.aligned.m16n8k16.row.col.f32.f16.f16.f32 " \
                 "{%0,%1,%2,%3}, {%4,%5,%6,%7}, {%8,%9}, {%0,%1,%2,%3};" \
                 : "+f"((c)[0]), "+f"((c)[1]), "+f"((c)[2]), "+f"((c)[3]) \
                 : "r"((a)[0]), "r"((a)[1]), "r"((a)[2]), "r"((a)[3]), \
                   "r"((b)[0]), "r"((b)[1]))
#define MMA_F16_2(c, a, b0, b1) \
    asm volatile("mma.sync.aligned.m16n8k16.row.col.f32.f16.f16.f32 " \
                 "{%0,%1,%2,%3}, {%4,%5,%6,%7}, {%8,%9}, {%0,%1,%2,%3};" \
                 : "+f"((c)[0]), "+f"((c)[1]), "+f"((c)[2]), "+f"((c)[3]) \
                 : "r"((a)[0]), "r"((a)[1]), "r"((a)[2]), "r"((a)[3]), \
                   "r"(b0), "r"(b1))

// ---------------------------------------------------------------------------
// Fused fp32 -> fp16 convert across 6 tensors (1 launch)
// ---------------------------------------------------------------------------
struct CvtArgs {
    const float* src[6];
    __half* dst[6];
    int cum[7];     // cumulative n8 offsets; cum[6] = total
};

__global__ void cvt6_kernel(CvtArgs args)
{
    int i = blockIdx.x * blockDim.x + threadIdx.x;
    if (i >= args.cum[6]) return;
    int seg = 0;
#pragma unroll
    for (int s = 1; s < 6; s++) if (i >= args.cum[s]) seg = s;
    const int local = i - args.cum[seg];
    const float* src = args.src[seg];
    __half* dst = args.dst[seg];
    float4 a = ((const float4*)src)[2 * local];
    float4 b = ((const float4*)src)[2 * local + 1];
    uint4 o;
    o.x = packh2(a.x, a.y);
    o.y = packh2(a.z, a.w);
    o.z = packh2(b.x, b.y);
    o.w = packh2(b.z, b.w);
    ((uint4*)dst)[local] = o;
}

// ---------------------------------------------------------------------------
// fp16 mma.sync GEMM (dense):  Y = (A @ B^T + bias) * scale
// mode 0: fp32 out plain; mode 1: Q head-split fp16 (scaled).
// CTA 128x128, 8 warps (2Mx4N), K-chunk 64, 3-stage cp.async pipeline.
// ---------------------------------------------------------------------------
#define KCH 64
#define TSTR 144                   // 128 B data + 16 pad
#define TILE_B (128 * TSTR)        // 18432
#define STAGE_B (2 * TILE_B)       // 36864
#define NSTAGE 3
#define GEMM_SMEM (NSTAGE * STAGE_B + 128)
#define NK (DM / KCH)              // 16

__global__ __launch_bounds__(256, 1) void gemm_mma(
    const __half* __restrict__ A, const __half* __restrict__ B,
    const float* __restrict__ bias, float* __restrict__ Yf,
    __half* __restrict__ Yh, float scale, int mode)
{
    extern __shared__ char dsm[];
    const uint32_t sb0 = (smem_u32(dsm) + 127) & ~127u;

    const int tid = threadIdx.x;
    const int lane = tid & 31;
    const int wid = tid >> 5;
    const int warpM = wid >> 2;
    const int warpN = wid & 3;
    const int bn = blockIdx.x * 128;
    const int bm = blockIdx.y * 128;

    // loader: 4 iters x 256 threads = 1024 x 16B = 128 rows x 128 B
    int lrow[4], lcc[4]; uint32_t soff[4];
#pragma unroll
    for (int i = 0; i < 4; i++) {
        const int id = tid + i * 256;
        lrow[i] = id >> 3;
        lcc[i] = (id & 7) * 8;     // half offset within k-chunk
        soff[i] = (uint32_t)(lrow[i] * TSTR + (id & 7) * 16);
    }

    const uint32_t aoff = (uint32_t)((warpM * 64 + (lane & 7) + ((lane >> 3) & 1) * 8) * TSTR
                                     + ((lane >> 4) & 1) * 16);
    const uint32_t boff = (uint32_t)((warpN * 32 + (lane & 7) + ((lane >> 4) & 1) * 8) * TSTR
                                     + ((lane >> 3) & 1) * 16);

    float c[4][4][4];
#pragma unroll
    for (int mf = 0; mf < 4; mf++)
#pragma unroll
        for (int nf = 0; nf < 4; nf++)
#pragma unroll
            for (int k = 0; k < 4; k++) c[mf][nf][k] = 0.0f;

    auto issue = [&](int s, int kc) {
        const uint32_t sb = sb0 + s * STAGE_B;
        const int ko = kc * KCH;
#pragma unroll
        for (int i = 0; i < 4; i++) {
            const long ag = (long)(bm + lrow[i]) * DM + ko + lcc[i];
            const long bg = (long)(bn + lrow[i]) * DM + ko + lcc[i];
            CP_ASYNC16(sb + 0 * TILE_B + soff[i], (const char*)(A + ag));
            CP_ASYNC16(sb + 1 * TILE_B + soff[i], (const char*)(B + bg));
        }
        CP_COMMIT();
    };

    issue(0, 0); issue(1, 1);

    for (int kt = 0; kt < NK; kt++) {
        if (kt + 1 < NK) CP_WAIT1(); else CP_WAIT0();
        __syncthreads();

        const uint32_t sb = sb0 + (kt % NSTAGE) * STAGE_B;
#pragma unroll
        for (int ks = 0; ks < 4; ks++) {
            const uint32_t kadd = (uint32_t)(ks * 32);
            uint32_t a[4][4], bfr[4][2];
#pragma unroll
            for (int mf = 0; mf < 4; mf++)
                LDSM_X4(a[mf][0], a[mf][1], a[mf][2], a[mf][3],
                        sb + 0 * TILE_B + aoff + kadd + (uint32_t)(mf * 16 * TSTR));
#pragma unroll
            for (int np = 0; np < 2; np++)
                LDSM_X4(bfr[np * 2][0], bfr[np * 2][1], bfr[np * 2 + 1][0], bfr[np * 2 + 1][1],
                        sb + 1 * TILE_B + boff + kadd + (uint32_t)(np * 16 * TSTR));
#pragma unroll
            for (int mf = 0; mf < 4; mf++)
#pragma unroll
                for (int nf = 0; nf < 4; nf++)
                    MMA_F16(c[mf][nf], a[mf], bfr[nf]);
        }
        __syncthreads();
        if (kt + 2 < NK) issue((kt + 2) % NSTAGE, kt + 2);
    }

    const int rb = bm + warpM * 64 + (lane >> 2);
    const int cb = bn + warpN * 32 + (lane & 3) * 2;
#pragma unroll
    for (int mf = 0; mf < 4; mf++) {
#pragma unroll
        for (int nf = 0; nf < 4; nf++) {
            const int col = cb + nf * 8;
            const float b0 = __ldg(&bias[col]);
            const float b1 = __ldg(&bias[col + 1]);
#pragma unroll
            for (int half = 0; half < 2; half++) {
                const int row = rb + mf * 16 + half * 8;
                float v0 = (c[mf][nf][half * 2 + 0] + b0) * scale;
                float v1 = (c[mf][nf][half * 2 + 1] + b1) * scale;
                if (mode == 0) {
                    float2 v; v.x = v0; v.y = v1;
                    *(float2*)&Yf[row * DM + col] = v;
                } else {
                    const int b = row >> 10, t = row & 1023;
                    const int h = col >> 6, d = col & 63;
                    const int dst = ((b * NH + h) * TT + t) * HD + d;
                    *(uint32_t*)(Yh + dst) = packh2(v0, v1);
                }
            }
        }
    }
}

// ---------------------------------------------------------------------------
// K/V projection GEMM, stride-aware (46.9% of dense work).
// grid (2, 240): y in [0,128) g0, [128,192) g1, [192,224) g2, [224,240) g3.
// ---------------------------------------------------------------------------
__global__ __launch_bounds__(256, 1) void gemm_kv(
    const __half* __restrict__ A, const __half* __restrict__ B,
    const float* __restrict__ bias, __half* __restrict__ Yh)
{
    extern __shared__ char dsm[];
    const uint32_t sb0 = (smem_u32(dsm) + 127) & ~127u;

    const int tid = threadIdx.x;
    const int lane = tid & 31;
    const int wid = tid >> 5;
    const int warpM = wid >> 2;
    const int warpN = wid & 3;
    const int bn = blockIdx.x * 128;

    const int ty = blockIdx.y;
    int g, mt;
    if (ty < 128)      { g = 0; mt = ty; }
    else if (ty < 192) { g = 1; mt = ty - 128; }
    else if (ty < 224) { g = 2; mt = ty - 192; }
    else               { g = 3; mt = ty - 224; }
    const int logSh = 12 - g;
    const int shMask = (1 << logSh) - 1;
    const int bm = mt * 128;

    uint32_t soff[4];
    long arow[4], brow[4];
#pragma unroll
    for (int i = 0; i < 4; i++) {
        const int id = tid + i * 256;
        const int r0 = id >> 3;
        const int cc = (id & 7) * 8;
        soff[i] = (uint32_t)(r0 * TSTR + (id & 7) * 16);
        const int r = bm + r0;
        const int b = r >> logSh, sc = r & shMask;
        arow[i] = ((long)b * SS + ((long)sc << g)) * DM + cc;
        const int col = bn + r0;
        brow[i] = (long)(64 * g + ((col >> 6) << 8) + (col & 63)) * DM + cc;
    }

    const uint32_t aoff = (uint32_t)((warpM * 64 + (lane & 7) + ((lane >> 3) & 1) * 8) * TSTR
                                     + ((lane >> 4) & 1) * 16);
    const uint32_t boff = (uint32_t)((warpN * 32 + (lane & 7) + ((lane >> 4) & 1) * 8) * TSTR
                                     + ((lane >> 3) & 1) * 16);

    float c[4][4][4];
#pragma unroll
    for (int mf = 0; mf < 4; mf++)
#pragma unroll
        for (int nf = 0; nf < 4; nf++)
#pragma unroll
            for (int k = 0; k < 4; k++) c[mf][nf][k] = 0.0f;

    auto issue = [&](int s, int kc) {
        const uint32_t sb = sb0 + s * STAGE_B;
        const int ko = kc * KCH;
#pragma unroll
        for (int i = 0; i < 4; i++) {
            CP_ASYNC16(sb + 0 * TILE_B + soff[i], (const char*)(A + arow[i] + ko));
            CP_ASYNC16(sb + 1 * TILE_B + soff[i], (const char*)(B + brow[i] + ko));
        }
        CP_COMMIT();
    };

    issue(0, 0); issue(1, 1);

    for (int kt = 0; kt < NK; kt++) {
        if (kt + 1 < NK) CP_WAIT1(); else CP_WAIT0();
        __syncthreads();

        const uint32_t sb = sb0 + (kt % NSTAGE) * STAGE_B;
#pragma unroll
        for (int ks = 0; ks < 4; ks++) {
            const uint32_t kadd = (uint32_t)(ks * 32);
            uint32_t a[4][4], bfr[4][2];
#pragma unroll
            for (int mf = 0; mf < 4; mf++)
                LDSM_X4(a[mf][0], a[mf][1], a[mf][2], a[mf][3],
                        sb + 0 * TILE_B + aoff + kadd + (uint32_t)(mf * 16 * TSTR));
#pragma unroll
            for (int np = 0; np < 2; np++)
                LDSM_X4(bfr[np * 2][0], bfr[np * 2][1], bfr[np * 2 + 1][0], bfr[np * 2 + 1][1],
                        sb + 1 * TILE_B + boff + kadd + (uint32_t)(np * 16 * TSTR));
#pragma unroll
            for (int mf = 0; mf < 4; mf++)
#pragma unroll
                for (int nf = 0; nf < 4; nf++)
                    MMA_F16(c[mf][nf], a[mf], bfr[nf]);
        }
        __syncthreads();
        if (kt + 2 < NK) issue((kt + 2) % NSTAGE, kt + 2);
    }

    const int rb = bm + warpM * 64 + (lane >> 2);
    const int cb = bn + warpN * 32 + (lane & 3) * 2;
#pragma unroll
    for (int mf = 0; mf < 4; mf++) {
#pragma unroll
        for (int nf = 0; nf < 4; nf++) {
            const int col = cb + nf * 8;
            const int head = g + ((col >> 6) << 2);
            const int d = col & 63;
            const int wr = head * 64 + d;
            const float b0 = __ldg(&bias[wr]);
            const float b1 = __ldg(&bias[wr + 1]);
#pragma unroll
            for (int half = 0; half < 2; half++) {
                const int row = rb + mf * 16 + half * 8;
                const int b = row >> logSh, sc = row & shMask;
                const int dst = ((b * NH + head) * SS + sc) * HD + d;
                *(uint32_t*)(Yh + dst) = packh2(c[mf][nf][half * 2 + 0] + b0,
                                                c[mf][nf][half * 2 + 1] + b1);
            }
        }
    }
}

// ---------------------------------------------------------------------------
// fp16 flash attention, 128-key chunks (one softmax pass per 128 keys).
// CTA: 128 q-rows (8 warps x m16), double-buffered K/V.
// ---------------------------------------------------------------------------
#define APITCH 144
#define KVARR (128 * APITCH)       // 18432 per K or V tile
#define ASTG (2 * KVARR)           // 36864
#define AQ_B (128 * APITCH)        // 18432
#define ATT_SMEM (AQ_B + 2 * ASTG + 128)

__global__ __launch_bounds__(256, 1) void attn_mma()
{
    extern __shared__ char asm_[];
    const uint32_t sb = (smem_u32(asm_) + 127) & ~127u;
    const uint32_t sQ = sb;
    const uint32_t sStg = sb + AQ_B;

    const int tid = threadIdx.x;
    const int lane = tid & 31;
    const int wid = tid >> 5;
    const int qt = blockIdx.x;
    const int h  = blockIdx.y;
    const int b  = blockIdx.z;
    const int nchunk = 32 >> (h & 3);      // S_h / 128

    const __half* Qg = g_q + ((size_t)(b * NH + h) * TT + qt * 128) * HD;
    const size_t kvbase = (size_t)(b * NH + h) * SS * HD;

    auto issue_kv = [&](int st, int kc) {
        const uint32_t s0 = sStg + st * ASTG;
#pragma unroll
        for (int i = 0; i < 4; i++) {
            const int idx = tid + i * 256;
            const int row = idx >> 3, cc = idx & 7;
            const size_t g = kvbase + (size_t)(kc * 128 + row) * HD + cc * 8;
            const uint32_t d = (uint32_t)(row * APITCH + cc * 16);
            CP_ASYNC16(s0 + 0 * KVARR + d, (const char*)(g_k + g));
            CP_ASYNC16(s0 + 1 * KVARR + d, (const char*)(g_v + g));
        }
        CP_COMMIT();
    };

#pragma unroll
    for (int i = 0; i < 4; i++) {
        const int idx = tid + i * 256;
        const int row = idx >> 3, cc = idx & 7;
        const uint32_t d = (uint32_t)(row * APITCH + cc * 16);
        CP_ASYNC16(sQ + d, (const char*)(Qg + row * HD + cc * 8));
    }
    issue_kv(0, 0);
    issue_kv(1, 1);

    const uint32_t aoff = (uint32_t)((wid * 16 + (lane & 7) + ((lane >> 3) & 1) * 8) * APITCH
                                     + ((lane >> 4) & 1) * 16);
    const uint32_t koff = (uint32_t)(((lane & 7) + ((lane >> 4) & 1) * 8) * APITCH
                                     + ((lane >> 3) & 1) * 16);
    const uint32_t voff = (uint32_t)((lane & 15) * APITCH + (lane >> 4) * 16);

    uint32_t ah[4][4];
    float o[8][4];
#pragma unroll
    for (int nf = 0; nf < 8; nf++)
#pragma unroll
        for (int k = 0; k < 4; k++) o[nf][k] = 0.0f;
    float m0 = -1e30f, m1 = -1e30f, l0 = 0.0f, l1 = 0.0f;

    for (int kc = 0; kc < nchunk; kc++) {
        if (kc + 1 < nchunk) CP_WAIT1(); else CP_WAIT0();
        __syncthreads();

        if (kc == 0) {
#pragma unroll
            for (int ks = 0; ks < 4; ks++)
                LDSM_X4(ah[ks][0], ah[ks][1], ah[ks][2], ah[ks][3], sQ + aoff + ks * 32);
        }

        const uint32_t s0 = sStg + (kc & 1) * ASTG;

        // ---- S = Q K^T over 128 keys --------------------------------------
        float S[16][4];
#pragma unroll
        for (int nf = 0; nf < 16; nf++)
#pragma unroll
            for (int k = 0; k < 4; k++) S[nf][k] = 0.0f;

#pragma unroll
        for (int ks = 0; ks < 4; ks++) {
#pragma unroll
            for (int np = 0; np < 8; np++) {
                uint32_t k0, k1, k2, k3;
                const uint32_t ka = koff + (uint32_t)(np * 16 * APITCH) + ks * 32;
                LDSM_X4(k0, k1, k2, k3, s0 + 0 * KVARR + ka);
                MMA_F16_2(S[2 * np],     ah[ks], k0, k1);
                MMA_F16_2(S[2 * np + 1], ah[ks], k2, k3);
            }
        }

        // ---- single softmax pass per 128 keys -----------------------------
        float mx0 = -1e30f, mx1 = -1e30f;
#pragma unroll
        for (int nf = 0; nf < 16; nf++) {
            mx0 = fmaxf(mx0, fmaxf(S[nf][0], S[nf][1]));
            mx1 = fmaxf(mx1, fmaxf(S[nf][2], S[nf][3]));
        }
        mx0 = fmaxf(mx0, __shfl_xor_sync(0xffffffffu, mx0, 1));
        mx0 = fmaxf(mx0, __shfl_xor_sync(0xffffffffu, mx0, 2));
        mx1 = fmaxf(mx1, __shfl_xor_sync(0xffffffffu, mx1, 1));
        mx1 = fmaxf(mx1, __shfl_xor_sync(0xffffffffu, mx1, 2));
        const float mn0 = fmaxf(m0, mx0), mn1 = fmaxf(m1, mx1);
        const float sc0 = ex2f(m0 - mn0), sc1 = ex2f(m1 - mn1);
        m0 = mn0; m1 = mn1;
        l0 *= sc0; l1 *= sc1;
#pragma unroll
        for (int nf = 0; nf < 8; nf++) {
            o[nf][0] *= sc0; o[nf][1] *= sc0;
            o[nf][2] *= sc1; o[nf][3] *= sc1;
        }

        uint32_t ph[8][4];
#pragma unroll
        for (int nf = 0; nf < 16; nf++) {
            const float p0 = ex2f(S[nf][0] - mn0);
            const float p1 = ex2f(S[nf][1] - mn0);
            const float p2 = ex2f(S[nf][2] - mn1);
            const float p3 = ex2f(S[nf][3] - mn1);
            l0 += p0 + p1; l1 += p2 + p3;
            const int ks = nf >> 1, sl = (nf & 1) * 2;
            ph[ks][sl + 0] = packh2(p0, p1);
            ph[ks][sl + 1] = packh2(p2, p3);
        }

        // ---- O += P V (8 k-steps of 16 keys) ------------------------------
#pragma unroll
        for (int ks = 0; ks < 8; ks++) {
#pragma unroll
            for (int nd = 0; nd < 4; nd++) {
                uint32_t v0, v1, v2, v3;
                const uint32_t va = voff + (uint32_t)(ks * 16 * APITCH) + (uint32_t)(nd * 32);
                LDSM_X4_T(v0, v1, v2, v3, s0 + 1 * KVARR + va);
                MMA_F16_2(o[2 * nd],     ph[ks], v0, v1);
                MMA_F16_2(o[2 * nd + 1], ph[ks], v2, v3);
            }
        }

        __syncthreads();
        if (kc + 2 < nchunk) issue_kv(kc & 1, kc + 2);
    }

    l0 += __shfl_xor_sync(0xffffffffu, l0, 1);
    l0 += __shfl_xor_sync(0xffffffffu, l0, 2);
    l1 += __shfl_xor_sync(0xffffffffu, l1, 1);
    l1 += __shfl_xor_sync(0xffffffffu, l1, 2);
    const float inv0 = 1.0f / l0, inv1 = 1.0f / l1;
    const int t0 = qt * 128 + wid * 16 + (lane >> 2);
    const size_t base0 = (size_t)(b * TT + t0) * DM + h * HD;
    const size_t base1 = base0 + 8 * DM;
#pragma unroll
    for (int nf = 0; nf < 8; nf++) {
        const int d = nf * 8 + (lane & 3) * 2;
        *(uint32_t*)(g_att + base0 + d) = packh2(o[nf][0] * inv0, o[nf][1] * inv0);
        *(uint32_t*)(g_att + base1 + d) = packh2(o[nf][2] * inv1, o[nf][3] * inv1);
    }
}

// ---------------------------------------------------------------------------
extern "C" void kernel_launch(void* const* d_in, const int* in_sizes, int n_in,
                              void* d_out, int out_size)
{
    const float* dec = (const float*)d_in[0];
    const float* enc = (const float*)d_in[1];
    const float* Wq  = (const float*)d_in[2];
    const float* bq  = (const float*)d_in[3];
    const float* Wk  = (const float*)d_in[4];
    const float* bk  = (const float*)d_in[5];
    const float* Wv  = (const float*)d_in[6];
    const float* bv  = (const float*)d_in[7];
    const float* Wo  = (const float*)d_in[8];
    const float* bo  = (const float*)d_in[9];

    __half *q_, *k_, *v_, *dec_, *enc_, *wq_, *wk_, *wv_, *wo_, *att_;
    cudaGetSymbolAddress((void**)&q_, g_q);
    cudaGetSymbolAddress((void**)&k_, g_k);
    cudaGetSymbolAddress((void**)&v_, g_v);
    cudaGetSymbolAddress((void**)&dec_, g_dec);
    cudaGetSymbolAddress((void**)&enc_, g_enc);
    cudaGetSymbolAddress((void**)&wq_, g_wq);
    cudaGetSymbolAddress((void**)&wk_, g_wk);
    cudaGetSymbolAddress((void**)&wv_, g_wv);
    cudaGetSymbolAddress((void**)&wo_, g_wo);
    cudaGetSymbolAddress((void**)&att_, g_att);

    cudaFuncSetAttribute((const void*)gemm_mma,
                         cudaFuncAttributeMaxDynamicSharedMemorySize, GEMM_SMEM);
    cudaFuncSetAttribute((const void*)gemm_kv,
                         cudaFuncAttributeMaxDynamicSharedMemorySize, GEMM_SMEM);
    cudaFuncSetAttribute((const void*)attn_mma,
                         cudaFuncAttributeMaxDynamicSharedMemorySize, ATT_SMEM);

    // one fused convert launch
    CvtArgs ca;
    const int nDec = BB * TT * DM / 8, nEnc = BB * SS * DM / 8, nW = DM * DM / 8;
    ca.src[0] = dec; ca.dst[0] = dec_;
    ca.src[1] = enc; ca.dst[1] = enc_;
    ca.src[2] = Wq;  ca.dst[2] = wq_;
    ca.src[3] = Wk;  ca.dst[3] = wk_;
    ca.src[4] = Wv;  ca.dst[4] = wv_;
    ca.src[5] = Wo;  ca.dst[5] = wo_;
    ca.cum[0] = 0;
    ca.cum[1] = nDec;
    ca.cum[2] = nDec + nEnc;
    ca.cum[3] = nDec + nEnc + nW;
    ca.cum[4] = nDec + nEnc + 2 * nW;
    ca.cum[5] = nDec + nEnc + 3 * nW;
    ca.cum[6] = nDec + nEnc + 4 * nW;
    cvt6_kernel<<<(ca.cum[6] + 255) / 256, 256>>>(ca);

    gemm_mma<<<dim3(8, 32), 256, GEMM_SMEM>>>(dec_, wq_, bq, nullptr, q_, SCALE_Q, 1);
    gemm_kv<<<dim3(2, 240), 256, GEMM_SMEM>>>(enc_, wk_, bk, k_);
    gemm_kv<<<dim3(2, 240), 256, GEMM_SMEM>>>(enc_, wv_, bv, v_);

    attn_mma<<<dim3(TT / 128, NH, BB), 256, ATT_SMEM>>>();

    gemm_mma<<<dim3(8, 32), 256, GEMM_SMEM>>>(att_, wo_, bo, (float*)d_out, nullptr, 1.0f, 0);
}

// round 12
// speedup vs baseline: 8.2338x; 1.1285x over previous
#include <cuda_runtime.h>
#include <cuda_fp16.h>
#include <math.h>
#include <stdint.h>

#define DM 1024
#define NH 16
#define HD 64
#define BB 4
#define TT 1024
#define SS 4096

#define SCALE_Q 0.1803368801111204f   // 0.125 * log2(e)

// ---------------- scratch (__device__ globals) ------------------------------
__device__ __half g_q[BB * NH * TT * HD];
__device__ __half g_k[BB * NH * SS * HD];
__device__ __half g_v[BB * NH * SS * HD];

__device__ __half g_dec[BB * TT * DM];
__device__ __half g_enc[BB * SS * DM];
__device__ __half g_wq[DM * DM], g_wk[DM * DM], g_wv[DM * DM], g_wo[DM * DM];
__device__ __half g_att[BB * TT * DM];

// ---------------- helpers ---------------------------------------------------
__device__ __forceinline__ uint32_t smem_u32(const void* p) {
    uint32_t a;
    asm("{ .reg .u64 t; cvta.to.shared.u64 t, %1; cvt.u32.u64 %0, t; }"
        : "=r"(a) : "l"(p));
    return a;
}
__device__ __forceinline__ float ex2f(float x) {
    float y;
    asm("ex2.approx.ftz.f32 %0, %1;" : "=f"(y) : "f"(x));
    return y;
}
__device__ __forceinline__ uint32_t packh2(float a, float b) {
    __half2 t = __floats2half2_rn(a, b);
    return *(uint32_t*)&t;
}

#define CP_ASYNC16(sa, ga) \
    asm volatile("cp.async.cg.shared.global [%0], [%1], 16;" :: "r"(sa), "l"(ga))
#define CP_COMMIT() asm volatile("cp.async.commit_group;" ::: "memory")
#define CP_WAIT1()  asm volatile("cp.async.wait_group 1;" ::: "memory")
#define CP_WAIT0()  asm volatile("cp.async.wait_group 0;" ::: "memory")

#define LDSM_X4(r0, r1, r2, r3, a) \
    asm volatile("ldmatrix.sync.aligned.m8n8.x4.shared.b16 {%0,%1,%2,%3}, [%4];" \
                 : "=r"(r0), "=r"(r1), "=r"(r2), "=r"(r3) : "r"(a))
#define LDSM_X4_T(r0, r1, r2, r3, a) \
    asm volatile("ldmatrix.sync.aligned.m8n8.x4.trans.shared.b16 {%0,%1,%2,%3}, [%4];" \
                 : "=r"(r0), "=r"(r1), "=r"(r2), "=r"(r3) : "r"(a))

#define MMA_F16(c, a, b) \
    asm volatile("mma.sync.aligned.m16n8k16.row.col.f32.f16.f16.f32 " \
                 "{%0,%1,%2,%3}, {%4,%5,%6,%7}, {%8,%9}, {%0,%1,%2,%3};" \
                 : "+f"((c)[0]), "+f"((c)[1]), "+f"((c)[2]), "+f"((c)[3]) \
                 : "r"((a)[0]), "r"((a)[1]), "r"((a)[2]), "r"((a)[3]), \
                   "r"((b)[0]), "r"((b)[1]))
#define MMA_F16_2(c, a, b0, b1) \
    asm volatile("mma.sync.aligned.m16n8k16.row.col.f32.f16.f16.f32 " \
                 "{%0,%1,%2,%3}, {%4,%5,%6,%7}, {%8,%9}, {%0,%1,%2,%3};" \
                 : "+f"((c)[0]), "+f"((c)[1]), "+f"((c)[2]), "+f"((c)[3]) \
                 : "r"((a)[0]), "r"((a)[1]), "r"((a)[2]), "r"((a)[3]), \
                   "r"(b0), "r"(b1))

// ---------------------------------------------------------------------------
// Fused fp32 -> fp16 convert across 6 tensors (1 launch)
// ---------------------------------------------------------------------------
struct CvtArgs {
    const float* src[6];
    __half* dst[6];
    int cum[7];
};

__global__ void cvt6_kernel(CvtArgs args)
{
    int i = blockIdx.x * blockDim.x + threadIdx.x;
    if (i >= args.cum[6]) return;
    int seg = 0;
#pragma unroll
    for (int s = 1; s < 6; s++) if (i >= args.cum[s]) seg = s;
    const int local = i - args.cum[seg];
    const float* src = args.src[seg];
    __half* dst = args.dst[seg];
    float4 a = ((const float4*)src)[2 * local];
    float4 b = ((const float4*)src)[2 * local + 1];
    uint4 o;
    o.x = packh2(a.x, a.y);
    o.y = packh2(a.z, a.w);
    o.z = packh2(b.x, b.y);
    o.w = packh2(b.z, b.w);
    ((uint4*)dst)[local] = o;
}

// ---------------------------------------------------------------------------
// fp16 mma.sync GEMM (dense). Register-lean inner loop + launch_bounds(256,2)
// -> 2 CTAs/SM (was register-limited to 1 at 154 regs; tensor pipe 34%).
// ---------------------------------------------------------------------------
#define KCH 64
#define TSTR 144
#define TILE_B (128 * TSTR)        // 18432
#define STAGE_B (2 * TILE_B)       // 36864
#define NSTAGE 3
#define GEMM_SMEM (NSTAGE * STAGE_B + 128)
#define NK (DM / KCH)              // 16

__global__ __launch_bounds__(256, 2) void gemm_mma(
    const __half* __restrict__ A, const __half* __restrict__ B,
    const float* __restrict__ bias, float* __restrict__ Yf,
    __half* __restrict__ Yh, float scale, int mode)
{
    extern __shared__ char dsm[];
    const uint32_t sb0 = (smem_u32(dsm) + 127) & ~127u;

    const int tid = threadIdx.x;
    const int lane = tid & 31;
    const int wid = tid >> 5;
    const int warpM = wid >> 2;
    const int warpN = wid & 3;
    const int bn = blockIdx.x * 128;
    const int bm = blockIdx.y * 128;

    const uint32_t aoff = (uint32_t)((warpM * 64 + (lane & 7) + ((lane >> 3) & 1) * 8) * TSTR
                                     + ((lane >> 4) & 1) * 16);
    const uint32_t boff = (uint32_t)((warpN * 32 + (lane & 7) + ((lane >> 4) & 1) * 8) * TSTR
                                     + ((lane >> 3) & 1) * 16);

    float c[4][4][4];
#pragma unroll
    for (int mf = 0; mf < 4; mf++)
#pragma unroll
        for (int nf = 0; nf < 4; nf++)
#pragma unroll
            for (int k = 0; k < 4; k++) c[mf][nf][k] = 0.0f;

    auto issue = [&](int s, int kc) {
        const uint32_t sb = sb0 + s * STAGE_B;
        const int ko = kc * KCH;
#pragma unroll
        for (int i = 0; i < 4; i++) {
            const int id = tid + i * 256;
            const int r = id >> 3, cc8 = (id & 7) * 8;
            const uint32_t so = (uint32_t)(r * TSTR + (id & 7) * 16);
            CP_ASYNC16(sb + 0 * TILE_B + so, (const char*)(A + (long)(bm + r) * DM + ko + cc8));
            CP_ASYNC16(sb + 1 * TILE_B + so, (const char*)(B + (long)(bn + r) * DM + ko + cc8));
        }
        CP_COMMIT();
    };

    issue(0, 0); issue(1, 1);

    for (int kt = 0; kt < NK; kt++) {
        if (kt + 1 < NK) CP_WAIT1(); else CP_WAIT0();
        __syncthreads();

        const uint32_t sb = sb0 + (kt % NSTAGE) * STAGE_B;
#pragma unroll
        for (int ks = 0; ks < 4; ks++) {
            const uint32_t kadd = (uint32_t)(ks * 32);
            uint32_t bfr[4][2];
#pragma unroll
            for (int np = 0; np < 2; np++)
                LDSM_X4(bfr[np * 2][0], bfr[np * 2][1], bfr[np * 2 + 1][0], bfr[np * 2 + 1][1],
                        sb + 1 * TILE_B + boff + kadd + (uint32_t)(np * 16 * TSTR));
#pragma unroll
            for (int mf = 0; mf < 4; mf++) {
                uint32_t a[4];
                LDSM_X4(a[0], a[1], a[2], a[3],
                        sb + 0 * TILE_B + aoff + kadd + (uint32_t)(mf * 16 * TSTR));
#pragma unroll
                for (int nf = 0; nf < 4; nf++)
                    MMA_F16(c[mf][nf], a, bfr[nf]);
            }
        }
        __syncthreads();
        if (kt + 2 < NK) issue((kt + 2) % NSTAGE, kt + 2);
    }

    const int rb = bm + warpM * 64 + (lane >> 2);
    const int cb = bn + warpN * 32 + (lane & 3) * 2;
#pragma unroll
    for (int mf = 0; mf < 4; mf++) {
#pragma unroll
        for (int nf = 0; nf < 4; nf++) {
            const int col = cb + nf * 8;
            const float b0 = __ldg(&bias[col]);
            const float b1 = __ldg(&bias[col + 1]);
#pragma unroll
            for (int half = 0; half < 2; half++) {
                const int row = rb + mf * 16 + half * 8;
                float v0 = (c[mf][nf][half * 2 + 0] + b0) * scale;
                float v1 = (c[mf][nf][half * 2 + 1] + b1) * scale;
                if (mode == 0) {
                    float2 v; v.x = v0; v.y = v1;
                    *(float2*)&Yf[row * DM + col] = v;
                } else {
                    const int b = row >> 10, t = row & 1023;
                    const int h = col >> 6, d = col & 63;
                    const int dst = ((b * NH + h) * TT + t) * HD + d;
                    *(uint32_t*)(Yh + dst) = packh2(v0, v1);
                }
            }
        }
    }
}

// ---------------------------------------------------------------------------
// K/V projection GEMM, stride-aware; same register-lean structure.
// grid (2, 240): y in [0,128) g0, [128,192) g1, [192,224) g2, [224,240) g3.
// ---------------------------------------------------------------------------
__global__ __launch_bounds__(256, 2) void gemm_kv(
    const __half* __restrict__ A, const __half* __restrict__ B,
    const float* __restrict__ bias, __half* __restrict__ Yh)
{
    extern __shared__ char dsm[];
    const uint32_t sb0 = (smem_u32(dsm) + 127) & ~127u;

    const int tid = threadIdx.x;
    const int lane = tid & 31;
    const int wid = tid >> 5;
    const int warpM = wid >> 2;
    const int warpN = wid & 3;
    const int bn = blockIdx.x * 128;

    const int ty = blockIdx.y;
    int g, mt;
    if (ty < 128)      { g = 0; mt = ty; }
    else if (ty < 192) { g = 1; mt = ty - 128; }
    else if (ty < 224) { g = 2; mt = ty - 192; }
    else               { g = 3; mt = ty - 224; }
    const int logSh = 12 - g;
    const int shMask = (1 << logSh) - 1;
    const int bm = mt * 128;

    const uint32_t aoff = (uint32_t)((warpM * 64 + (lane & 7) + ((lane >> 3) & 1) * 8) * TSTR
                                     + ((lane >> 4) & 1) * 16);
    const uint32_t boff = (uint32_t)((warpN * 32 + (lane & 7) + ((lane >> 4) & 1) * 8) * TSTR
                                     + ((lane >> 3) & 1) * 16);

    float c[4][4][4];
#pragma unroll
    for (int mf = 0; mf < 4; mf++)
#pragma unroll
        for (int nf = 0; nf < 4; nf++)
#pragma unroll
            for (int k = 0; k < 4; k++) c[mf][nf][k] = 0.0f;

    auto issue = [&](int s, int kc) {
        const uint32_t sb = sb0 + s * STAGE_B;
        const int ko = kc * KCH;
#pragma unroll
        for (int i = 0; i < 4; i++) {
            const int id = tid + i * 256;
            const int r0 = id >> 3, cc8 = (id & 7) * 8;
            const uint32_t so = (uint32_t)(r0 * TSTR + (id & 7) * 16);
            const int r = bm + r0;
            const int b = r >> logSh, sc = r & shMask;
            const long ar = ((long)b * SS + ((long)sc << g)) * DM + cc8;
            const int col = bn + r0;
            const long br = (long)(64 * g + ((col >> 6) << 8) + (col & 63)) * DM + cc8;
            CP_ASYNC16(sb + 0 * TILE_B + so, (const char*)(A + ar + ko));
            CP_ASYNC16(sb + 1 * TILE_B + so, (const char*)(B + br + ko));
        }
        CP_COMMIT();
    };

    issue(0, 0); issue(1, 1);

    for (int kt = 0; kt < NK; kt++) {
        if (kt + 1 < NK) CP_WAIT1(); else CP_WAIT0();
        __syncthreads();

        const uint32_t sb = sb0 + (kt % NSTAGE) * STAGE_B;
#pragma unroll
        for (int ks = 0; ks < 4; ks++) {
            const uint32_t kadd = (uint32_t)(ks * 32);
            uint32_t bfr[4][2];
#pragma unroll
            for (int np = 0; np < 2; np++)
                LDSM_X4(bfr[np * 2][0], bfr[np * 2][1], bfr[np * 2 + 1][0], bfr[np * 2 + 1][1],
                        sb + 1 * TILE_B + boff + kadd + (uint32_t)(np * 16 * TSTR));
#pragma unroll
            for (int mf = 0; mf < 4; mf++) {
                uint32_t a[4];
                LDSM_X4(a[0], a[1], a[2], a[3],
                        sb + 0 * TILE_B + aoff + kadd + (uint32_t)(mf * 16 * TSTR));
#pragma unroll
                for (int nf = 0; nf < 4; nf++)
                    MMA_F16(c[mf][nf], a, bfr[nf]);
            }
        }
        __syncthreads();
        if (kt + 2 < NK) issue((kt + 2) % NSTAGE, kt + 2);
    }

    const int rb = bm + warpM * 64 + (lane >> 2);
    const int cb = bn + warpN * 32 + (lane & 3) * 2;
#pragma unroll
    for (int mf = 0; mf < 4; mf++) {
#pragma unroll
        for (int nf = 0; nf < 4; nf++) {
            const int col = cb + nf * 8;
            const int head = g + ((col >> 6) << 2);
            const int d = col & 63;
            const int wr = head * 64 + d;
            const float b0 = __ldg(&bias[wr]);
            const float b1 = __ldg(&bias[wr + 1]);
#pragma unroll
            for (int half = 0; half < 2; half++) {
                const int row = rb + mf * 16 + half * 8;
                const int b = row >> logSh, sc = row & shMask;
                const int dst = ((b * NH + head) * SS + sc) * HD + d;
                *(uint32_t*)(Yh + dst) = packh2(c[mf][nf][half * 2 + 0] + b0,
                                                c[mf][nf][half * 2 + 1] + b1);
            }
        }
    }
}

// ---------------------------------------------------------------------------
// fp16 flash attention, 128-key chunks (unchanged from round 11).
// ---------------------------------------------------------------------------
#define APITCH 144
#define KVARR (128 * APITCH)
#define ASTG (2 * KVARR)
#define AQ_B (128 * APITCH)
#define ATT_SMEM (AQ_B + 2 * ASTG + 128)

__global__ __launch_bounds__(256, 1) void attn_mma()
{
    extern __shared__ char asm_[];
    const uint32_t sb = (smem_u32(asm_) + 127) & ~127u;
    const uint32_t sQ = sb;
    const uint32_t sStg = sb + AQ_B;

    const int tid = threadIdx.x;
    const int lane = tid & 31;
    const int wid = tid >> 5;
    const int qt = blockIdx.x;
    const int h  = blockIdx.y;
    const int b  = blockIdx.z;
    const int nchunk = 32 >> (h & 3);

    const __half* Qg = g_q + ((size_t)(b * NH + h) * TT + qt * 128) * HD;
    const size_t kvbase = (size_t)(b * NH + h) * SS * HD;

    auto issue_kv = [&](int st, int kc) {
        const uint32_t s0 = sStg + st * ASTG;
#pragma unroll
        for (int i = 0; i < 4; i++) {
            const int idx = tid + i * 256;
            const int row = idx >> 3, cc = idx & 7;
            const size_t g = kvbase + (size_t)(kc * 128 + row) * HD + cc * 8;
            const uint32_t d = (uint32_t)(row * APITCH + cc * 16);
            CP_ASYNC16(s0 + 0 * KVARR + d, (const char*)(g_k + g));
            CP_ASYNC16(s0 + 1 * KVARR + d, (const char*)(g_v + g));
        }
        CP_COMMIT();
    };

#pragma unroll
    for (int i = 0; i < 4; i++) {
        const int idx = tid + i * 256;
        const int row = idx >> 3, cc = idx & 7;
        const uint32_t d = (uint32_t)(row * APITCH + cc * 16);
        CP_ASYNC16(sQ + d, (const char*)(Qg + row * HD + cc * 8));
    }
    issue_kv(0, 0);
    issue_kv(1, 1);

    const uint32_t aoff = (uint32_t)((wid * 16 + (lane & 7) + ((lane >> 3) & 1) * 8) * APITCH
                                     + ((lane >> 4) & 1) * 16);
    const uint32_t koff = (uint32_t)(((lane & 7) + ((lane >> 4) & 1) * 8) * APITCH
                                     + ((lane >> 3) & 1) * 16);
    const uint32_t voff = (uint32_t)((lane & 15) * APITCH + (lane >> 4) * 16);

    uint32_t ah[4][4];
    float o[8][4];
#pragma unroll
    for (int nf = 0; nf < 8; nf++)
#pragma unroll
        for (int k = 0; k < 4; k++) o[nf][k] = 0.0f;
    float m0 = -1e30f, m1 = -1e30f, l0 = 0.0f, l1 = 0.0f;

    for (int kc = 0; kc < nchunk; kc++) {
        if (kc + 1 < nchunk) CP_WAIT1(); else CP_WAIT0();
        __syncthreads();

        if (kc == 0) {
#pragma unroll
            for (int ks = 0; ks < 4; ks++)
                LDSM_X4(ah[ks][0], ah[ks][1], ah[ks][2], ah[ks][3], sQ + aoff + ks * 32);
        }

        const uint32_t s0 = sStg + (kc & 1) * ASTG;

        float S[16][4];
#pragma unroll
        for (int nf = 0; nf < 16; nf++)
#pragma unroll
            for (int k = 0; k < 4; k++) S[nf][k] = 0.0f;

#pragma unroll
        for (int ks = 0; ks < 4; ks++) {
#pragma unroll
            for (int np = 0; np < 8; np++) {
                uint32_t k0, k1, k2, k3;
                const uint32_t ka = koff + (uint32_t)(np * 16 * APITCH) + ks * 32;
                LDSM_X4(k0, k1, k2, k3, s0 + 0 * KVARR + ka);
                MMA_F16_2(S[2 * np],     ah[ks], k0, k1);
                MMA_F16_2(S[2 * np + 1], ah[ks], k2, k3);
            }
        }

        float mx0 = -1e30f, mx1 = -1e30f;
#pragma unroll
        for (int nf = 0; nf < 16; nf++) {
            mx0 = fmaxf(mx0, fmaxf(S[nf][0], S[nf][1]));
            mx1 = fmaxf(mx1, fmaxf(S[nf][2], S[nf][3]));
        }
        mx0 = fmaxf(mx0, __shfl_xor_sync(0xffffffffu, mx0, 1));
        mx0 = fmaxf(mx0, __shfl_xor_sync(0xffffffffu, mx0, 2));
        mx1 = fmaxf(mx1, __shfl_xor_sync(0xffffffffu, mx1, 1));
        mx1 = fmaxf(mx1, __shfl_xor_sync(0xffffffffu, mx1, 2));
        const float mn0 = fmaxf(m0, mx0), mn1 = fmaxf(m1, mx1);
        const float sc0 = ex2f(m0 - mn0), sc1 = ex2f(m1 - mn1);
        m0 = mn0; m1 = mn1;
        l0 *= sc0; l1 *= sc1;
#pragma unroll
        for (int nf = 0; nf < 8; nf++) {
            o[nf][0] *= sc0; o[nf][1] *= sc0;
            o[nf][2] *= sc1; o[nf][3] *= sc1;
        }

        uint32_t ph[8][4];
#pragma unroll
        for (int nf = 0; nf < 16; nf++) {
            const float p0 = ex2f(S[nf][0] - mn0);
            const float p1 = ex2f(S[nf][1] - mn0);
            const float p2 = ex2f(S[nf][2] - mn1);
            const float p3 = ex2f(S[nf][3] - mn1);
            l0 += p0 + p1; l1 += p2 + p3;
            const int ks = nf >> 1, sl = (nf & 1) * 2;
            ph[ks][sl + 0] = packh2(p0, p1);
            ph[ks][sl + 1] = packh2(p2, p3);
        }

#pragma unroll
        for (int ks = 0; ks < 8; ks++) {
#pragma unroll
            for (int nd = 0; nd < 4; nd++) {
                uint32_t v0, v1, v2, v3;
                const uint32_t va = voff + (uint32_t)(ks * 16 * APITCH) + (uint32_t)(nd * 32);
                LDSM_X4_T(v0, v1, v2, v3, s0 + 1 * KVARR + va);
                MMA_F16_2(o[2 * nd],     ph[ks], v0, v1);
                MMA_F16_2(o[2 * nd + 1], ph[ks], v2, v3);
            }
        }

        __syncthreads();
        if (kc + 2 < nchunk) issue_kv(kc & 1, kc + 2);
    }

    l0 += __shfl_xor_sync(0xffffffffu, l0, 1);
    l0 += __shfl_xor_sync(0xffffffffu, l0, 2);
    l1 += __shfl_xor_sync(0xffffffffu, l1, 1);
    l1 += __shfl_xor_sync(0xffffffffu, l1, 2);
    const float inv0 = 1.0f / l0, inv1 = 1.0f / l1;
    const int t0 = qt * 128 + wid * 16 + (lane >> 2);
    const size_t base0 = (size_t)(b * TT + t0) * DM + h * HD;
    const size_t base1 = base0 + 8 * DM;
#pragma unroll
    for (int nf = 0; nf < 8; nf++) {
        const int d = nf * 8 + (lane & 3) * 2;
        *(uint32_t*)(g_att + base0 + d) = packh2(o[nf][0] * inv0, o[nf][1] * inv0);
        *(uint32_t*)(g_att + base1 + d) = packh2(o[nf][2] * inv1, o[nf][3] * inv1);
    }
}

// ---------------------------------------------------------------------------
extern "C" void kernel_launch(void* const* d_in, const int* in_sizes, int n_in,
                              void* d_out, int out_size)
{
    const float* dec = (const float*)d_in[0];
    const float* enc = (const float*)d_in[1];
    const float* Wq  = (const float*)d_in[2];
    const float* bq  = (const float*)d_in[3];
    const float* Wk  = (const float*)d_in[4];
    const float* bk  = (const float*)d_in[5];
    const float* Wv  = (const float*)d_in[6];
    const float* bv  = (const float*)d_in[7];
    const float* Wo  = (const float*)d_in[8];
    const float* bo  = (const float*)d_in[9];

    __half *q_, *k_, *v_, *dec_, *enc_, *wq_, *wk_, *wv_, *wo_, *att_;
    cudaGetSymbolAddress((void**)&q_, g_q);
    cudaGetSymbolAddress((void**)&k_, g_k);
    cudaGetSymbolAddress((void**)&v_, g_v);
    cudaGetSymbolAddress((void**)&dec_, g_dec);
    cudaGetSymbolAddress((void**)&enc_, g_enc);
    cudaGetSymbolAddress((void**)&wq_, g_wq);
    cudaGetSymbolAddress((void**)&wk_, g_wk);
    cudaGetSymbolAddress((void**)&wv_, g_wv);
    cudaGetSymbolAddress((void**)&wo_, g_wo);
    cudaGetSymbolAddress((void**)&att_, g_att);

    cudaFuncSetAttribute((const void*)gemm_mma,
                         cudaFuncAttributeMaxDynamicSharedMemorySize, GEMM_SMEM);
    cudaFuncSetAttribute((const void*)gemm_kv,
                         cudaFuncAttributeMaxDynamicSharedMemorySize, GEMM_SMEM);
    cudaFuncSetAttribute((const void*)attn_mma,
                         cudaFuncAttributeMaxDynamicSharedMemorySize, ATT_SMEM);

    CvtArgs ca;
    const int nDec = BB * TT * DM / 8, nEnc = BB * SS * DM / 8, nW = DM * DM / 8;
    ca.src[0] = dec; ca.dst[0] = dec_;
    ca.src[1] = enc; ca.dst[1] = enc_;
    ca.src[2] = Wq;  ca.dst[2] = wq_;
    ca.src[3] = Wk;  ca.dst[3] = wk_;
    ca.src[4] = Wv;  ca.dst[4] = wv_;
    ca.src[5] = Wo;  ca.dst[5] = wo_;
    ca.cum[0] = 0;
    ca.cum[1] = nDec;
    ca.cum[2] = nDec + nEnc;
    ca.cum[3] = nDec + nEnc + nW;
    ca.cum[4] = nDec + nEnc + 2 * nW;
    ca.cum[5] = nDec + nEnc + 3 * nW;
    ca.cum[6] = nDec + nEnc + 4 * nW;
    cvt6_kernel<<<(ca.cum[6] + 255) / 256, 256>>>(ca);

    gemm_mma<<<dim3(8, 32), 256, GEMM_SMEM>>>(dec_, wq_, bq, nullptr, q_, SCALE_Q, 1);
    gemm_kv<<<dim3(2, 240), 256, GEMM_SMEM>>>(enc_, wk_, bk, k_);
    gemm_kv<<<dim3(2, 240), 256, GEMM_SMEM>>>(enc_, wv_, bv, v_);

    attn_mma<<<dim3(TT / 128, NH, BB), 256, ATT_SMEM>>>();

    gemm_mma<<<dim3(8, 32), 256, GEMM_SMEM>>>(att_, wo_, bo, (float*)d_out, nullptr, 1.0f, 0);
}